// round 5
// baseline (speedup 1.0000x reference)
#include <cuda_runtime.h>
#include <cuda_bf16.h>
#include <mma.h>
#include <math.h>
#include <cstdint>

using namespace nvcuda;

#define Bb 4
#define Ss 512
#define Hh 768
#define Dd 24
#define Mm 96
#define OH 768
#define H3 2304
#define NROWS (Bb*Ss)   // 2048

typedef unsigned long long ull;

// ---- scratch ----
__device__ __align__(16) float g_Zj[NROWS*Dd];
__device__ __align__(16) float g_Zi[NROWS*Dd];
__device__ __align__(16) float g_Aj[NROWS*Mm];
__device__ __align__(16) float g_Bi[NROWS*Mm];
__device__ __align__(16) float g_ctx[(long)NROWS*Hh];
// bf16 hi/lo operands for tensor-core GEMMs
__device__ __align__(16) __nv_bfloat16 g_pbh[(long)Bb*Ss*Ss];
__device__ __align__(16) __nv_bfloat16 g_pbl[(long)Bb*Ss*Ss];
__device__ __align__(16) __nv_bfloat16 g_hih[(long)NROWS*Hh];
__device__ __align__(16) __nv_bfloat16 g_hil[(long)NROWS*Hh];
__device__ __align__(16) __nv_bfloat16 g_m1h[(long)NROWS*H3];
__device__ __align__(16) __nv_bfloat16 g_m1l[(long)NROWS*H3];
__device__ __align__(16) __nv_bfloat16 g_w1h[(long)OH*H3];
__device__ __align__(16) __nv_bfloat16 g_w1l[(long)OH*H3];
__device__ __align__(16) __nv_bfloat16 g_hidh[(long)NROWS*OH];
__device__ __align__(16) __nv_bfloat16 g_hidl[(long)NROWS*OH];
__device__ __align__(16) __nv_bfloat16 g_w2h[(long)Hh*OH];
__device__ __align__(16) __nv_bfloat16 g_w2l[(long)Hh*OH];

// ---- packed f32x2 helpers ----
__device__ __forceinline__ ull pack2(float lo, float hi){
    ull r; asm("mov.b64 %0, {%1, %2};" : "=l"(r) : "f"(lo), "f"(hi)); return r;
}
__device__ __forceinline__ void unpack2(ull v, float& lo, float& hi){
    asm("mov.b64 {%0, %1}, %2;" : "=f"(lo), "=f"(hi) : "l"(v));
}
__device__ __forceinline__ ull fma2(ull a, ull b, ull c){
    ull d; asm("fma.rn.f32x2 %0, %1, %2, %3;" : "=l"(d) : "l"(a), "l"(b), "l"(c));
    return d;
}
// bf16 hi/lo split
__device__ __forceinline__ void bsplit(float v, __nv_bfloat16& h, __nv_bfloat16& l){
    h = __float2bfloat16(v);
    l = __float2bfloat16(v - __bfloat162float(h));
}

// ============================================================
// K1: projections + rank-1 softmax-MLP terms
// ============================================================
__global__ __launch_bounds__(256) void proj_kernel(
    const float* __restrict__ Hj, const float* __restrict__ Hi,
    const float* __restrict__ pjw, const float* __restrict__ piw,
    const float* __restrict__ sw1)
{
    int r = blockIdx.x;
    __shared__ float shj[Hh], shi[Hh], szj[Dd], szi[Dd];
    int tid = threadIdx.x;
    for (int i = tid; i < Hh; i += 256){
        shj[i] = Hj[(long)r*Hh + i];
        shi[i] = Hi[(long)r*Hh + i];
    }
    __syncthreads();
    int o = tid >> 3, g = tid & 7;
    if (o < Dd){
        float pj = 0.f, pi = 0.f;
        for (int h = g; h < Hh; h += 8){
            pj += shj[h] * pjw[o*Hh + h];
            pi += shi[h] * piw[o*Hh + h];
        }
        #pragma unroll
        for (int d = 4; d > 0; d >>= 1){
            pj += __shfl_down_sync(0xffffffffu, pj, d, 8);
            pi += __shfl_down_sync(0xffffffffu, pi, d, 8);
        }
        if (g == 0){
            szj[o] = pj; szi[o] = pi;
            g_Zj[r*Dd + o] = pj; g_Zi[r*Dd + o] = pi;
        }
    }
    __syncthreads();
    if (tid < Mm){
        float a = 0.f, bsum = 0.f;
        #pragma unroll
        for (int d = 0; d < Dd; d++){
            a    += sw1[tid*96 +      d] * szj[d];
            bsum += sw1[tid*96 + 24 + d] * szi[d];
        }
        g_Aj[r*Mm + tid] = a;
        g_Bi[r*Mm + tid] = bsum;
    }
}

// ============================================================
// K2: pairwise logits + masked softmax -> probs (bf16 hi/lo out)
// ============================================================
__global__ __launch_bounds__(256) void pair_kernel(
    const float* __restrict__ sw1, const float* __restrict__ sb1,
    const float* __restrict__ sw2v, const float* __restrict__ sb2,
    const float* __restrict__ mask)
{
    int r = blockIdx.x;
    int b = r >> 9;
    __shared__ ulonglong2 sW[Mm][Dd/2];
    __shared__ float2 sCW[Mm];
    __shared__ float szj[Dd];
    __shared__ float sred[8];
    int tid = threadIdx.x;

    for (int i = tid; i < Mm*(Dd/2); i += 256){
        int m = i / (Dd/2), p = i % (Dd/2);
        int d0 = 2*p, d1 = 2*p + 1;
        ulonglong2 w;
        w.x = pack2(sw1[m*96 + 48 + d0], sw1[m*96 + 72 + d0]);
        w.y = pack2(sw1[m*96 + 48 + d1], sw1[m*96 + 72 + d1]);
        sW[m][p] = w;
    }
    if (tid < Mm) sCW[tid] = make_float2(g_Aj[r*Mm + tid] + sb1[tid], sw2v[tid]);
    if (tid < Dd) szj[tid] = g_Zj[r*Dd + tid];
    __syncthreads();

    int t0 = tid, t1 = tid + 256;
    const float* zi0 = &g_Zi[(long)(b*Ss + t0)*Dd];
    const float* zi1 = &g_Zi[(long)(b*Ss + t1)*Dd];
    ull uv0[Dd], uv1[Dd];
    #pragma unroll
    for (int d = 0; d < Dd; d++){
        float zj = szj[d];
        float z0 = __ldg(&zi0[d]);
        float z1 = __ldg(&zi1[d]);
        uv0[d] = pack2(zj*z0, fabsf(zj - z0));
        uv1[d] = pack2(zj*z1, fabsf(zj - z1));
    }

    const float4* bi0 = (const float4*)&g_Bi[(long)(b*Ss + t0)*Mm];
    const float4* bi1 = (const float4*)&g_Bi[(long)(b*Ss + t1)*Mm];
    float logit0 = 0.f, logit1 = 0.f;

    #pragma unroll 1
    for (int mg = 0; mg < Mm/4; mg++){
        float4 bv0 = __ldg(&bi0[mg]);
        float4 bv1 = __ldg(&bi1[mg]);
        float bb0[4] = {bv0.x, bv0.y, bv0.z, bv0.w};
        float bb1[4] = {bv1.x, bv1.y, bv1.z, bv1.w};
        #pragma unroll
        for (int j = 0; j < 4; j++){
            int m = mg*4 + j;
            ull h0 = 0ull, h1 = 0ull;
            #pragma unroll
            for (int p = 0; p < Dd/2; p++){
                ulonglong2 w = sW[m][p];
                h0 = fma2(uv0[2*p  ], w.x, h0);
                h1 = fma2(uv1[2*p  ], w.x, h1);
                h0 = fma2(uv0[2*p+1], w.y, h0);
                h1 = fma2(uv1[2*p+1], w.y, h1);
            }
            float a0,c0,a1,c1;
            unpack2(h0, a0, c0);
            unpack2(h1, a1, c1);
            float2 cw = sCW[m];
            float hv0 = cw.x + bb0[j] + a0 + c0;
            float hv1 = cw.x + bb1[j] + a1 + c1;
            logit0 += cw.y * fmaxf(hv0, 0.f);
            logit1 += cw.y * fmaxf(hv1, 0.f);
        }
    }
    float lt0 = logit0 + sb2[0] + (1.f - mask[b*Ss + t0]) * (-3.402823466e38f);
    float lt1 = logit1 + sb2[0] + (1.f - mask[b*Ss + t1]) * (-3.402823466e38f);

    float mx = fmaxf(lt0, lt1);
    #pragma unroll
    for (int d = 16; d > 0; d >>= 1)
        mx = fmaxf(mx, __shfl_xor_sync(0xffffffffu, mx, d));
    if ((tid & 31) == 0) sred[tid >> 5] = mx;
    __syncthreads();
    float bmax = sred[0];
    #pragma unroll
    for (int i = 1; i < 8; i++) bmax = fmaxf(bmax, sred[i]);

    float e0 = expf(lt0 - bmax);
    float e1 = expf(lt1 - bmax);
    float sm = e0 + e1;
    #pragma unroll
    for (int d = 16; d > 0; d >>= 1)
        sm += __shfl_xor_sync(0xffffffffu, sm, d);
    __syncthreads();
    if ((tid & 31) == 0) sred[tid >> 5] = sm;
    __syncthreads();
    float tot = 0.f;
    #pragma unroll
    for (int i = 0; i < 8; i++) tot += sred[i];
    float inv = 1.f / tot;

    __nv_bfloat16 h, l;
    bsplit(e0 * inv, h, l);
    g_pbh[(long)r*Ss + t0] = h; g_pbl[(long)r*Ss + t0] = l;
    bsplit(e1 * inv, h, l);
    g_pbh[(long)r*Ss + t1] = h; g_pbl[(long)r*Ss + t1] = l;
}

// ============================================================
// K3: fp32 -> bf16 hi/lo split (vectorized)
// ============================================================
__global__ __launch_bounds__(256) void conv_split(
    const float* __restrict__ x, __nv_bfloat16* __restrict__ hi,
    __nv_bfloat16* __restrict__ lo, int n4)
{
    int i = blockIdx.x*256 + threadIdx.x;
    if (i >= n4) return;
    float4 v = ((const float4*)x)[i];
    __nv_bfloat16 h0,h1,h2,h3,l0,l1,l2,l3;
    bsplit(v.x,h0,l0); bsplit(v.y,h1,l1); bsplit(v.z,h2,l2); bsplit(v.w,h3,l3);
    __nv_bfloat162 p0, p1;
    p0.x=h0; p0.y=h1; p1.x=h2; p1.y=h3;
    ((__nv_bfloat162*)hi)[2*i]   = p0;
    ((__nv_bfloat162*)hi)[2*i+1] = p1;
    p0.x=l0; p0.y=l1; p1.x=l2; p1.y=l3;
    ((__nv_bfloat162*)lo)[2*i]   = p0;
    ((__nv_bfloat162*)lo)[2*i+1] = p1;
}

// ============================================================
// K4: msg_in = [ctx | Hj | ctx*Hj] -> bf16 hi/lo
// ============================================================
__device__ __forceinline__ void store4(__nv_bfloat16* hp, __nv_bfloat16* lp,
                                       float a, float b, float c, float d)
{
    __nv_bfloat16 h0,h1,h2,h3,l0,l1,l2,l3;
    bsplit(a,h0,l0); bsplit(b,h1,l1); bsplit(c,h2,l2); bsplit(d,h3,l3);
    __nv_bfloat162 p0, p1;
    p0.x=h0; p0.y=h1; p1.x=h2; p1.y=h3;
    ((__nv_bfloat162*)hp)[0] = p0; ((__nv_bfloat162*)hp)[1] = p1;
    p0.x=l0; p0.y=l1; p1.x=l2; p1.y=l3;
    ((__nv_bfloat162*)lp)[0] = p0; ((__nv_bfloat162*)lp)[1] = p1;
}
__global__ __launch_bounds__(256) void msgin_conv(const float* __restrict__ Hj)
{
    int i = blockIdx.x*256 + threadIdx.x;
    if (i >= NROWS*(Hh/4)) return;
    int r = i / (Hh/4);
    int c = (i % (Hh/4)) * 4;
    float4 cv = *(const float4*)&g_ctx[(long)r*Hh + c];
    float4 hv = *(const float4*)&Hj[(long)r*Hh + c];
    long base = (long)r*H3 + c;
    store4(&g_m1h[base],      &g_m1l[base],      cv.x, cv.y, cv.z, cv.w);
    store4(&g_m1h[base+Hh],   &g_m1l[base+Hh],   hv.x, hv.y, hv.z, hv.w);
    store4(&g_m1h[base+2*Hh], &g_m1l[base+2*Hh],
           cv.x*hv.x, cv.y*hv.y, cv.z*hv.z, cv.w*hv.w);
}

// ============================================================
// K5: WMMA GEMM  C[M,N] = A[M,K] @ opB  (bf16 hi/lo, 3-pass)
//  CTA tile 128x128, 8 warps (32x64 each), K chunk 32.
//  TRANSB=true : B is [N,K] row-major (NT)
//  TRANSB=false: B is [K,N] row-major (NN)
//  EPI 0: +bias, relu -> g_hidh/g_hidl (bf16 split)
//  EPI 1: (+bias)*alpha -> Cout fp32
//  EPI 2: raw fp32 -> Cout (batched via blockIdx.z strides)
// ============================================================
template<bool TRANSB, int EPI>
__global__ __launch_bounds__(256) void gemm_wmma(
    const __nv_bfloat16* __restrict__ Ah, const __nv_bfloat16* __restrict__ Al,
    const __nv_bfloat16* __restrict__ Bh, const __nv_bfloat16* __restrict__ Bl,
    float* __restrict__ Cout, int N, int K, int ldA, int ldB,
    long strideA, long strideB, long strideC,
    const float* __restrict__ bias, const float* __restrict__ alpha_p)
{
    __shared__ __nv_bfloat16 As[2][128][40];
    __shared__ __nv_bfloat16 Bs[2][5120];   // NT: [n][40] ; NN: [k][136]

    int tid = threadIdx.x;
    int wid = tid >> 5, lane = tid & 31;
    int wr = wid & 3, wc = wid >> 2;        // 4x2 warps, warp tile 32x64
    long row0 = (long)blockIdx.y * 128;
    long col0 = (long)blockIdx.x * 128;

    const __nv_bfloat16* APh = Ah + (long)blockIdx.z * strideA;
    const __nv_bfloat16* APl = Al + (long)blockIdx.z * strideA;
    const __nv_bfloat16* BPh = Bh + (long)blockIdx.z * strideB;
    const __nv_bfloat16* BPl = Bl + (long)blockIdx.z * strideB;
    float* Cb = Cout ? (Cout + (long)blockIdx.z * strideC) : nullptr;

    wmma::fragment<wmma::accumulator,16,16,16,float> acc[2][4];
    #pragma unroll
    for (int i = 0; i < 2; i++)
        #pragma unroll
        for (int j = 0; j < 4; j++) wmma::fill_fragment(acc[i][j], 0.f);

    #pragma unroll 1
    for (int kc = 0; kc < K; kc += 32){
        // stage A (128x32, hi+lo)
        #pragma unroll
        for (int t = tid; t < 512; t += 256){
            int r = t >> 2, seg = t & 3;
            long off = (row0 + r)*(long)ldA + kc + seg*8;
            *(float4*)&As[0][r][seg*8] = *(const float4*)(APh + off);
            *(float4*)&As[1][r][seg*8] = *(const float4*)(APl + off);
        }
        // stage B
        if (TRANSB){
            #pragma unroll
            for (int t = tid; t < 512; t += 256){
                int r = t >> 2, seg = t & 3;
                long off = (col0 + r)*(long)ldB + kc + seg*8;
                *(float4*)&Bs[0][r*40 + seg*8] = *(const float4*)(BPh + off);
                *(float4*)&Bs[1][r*40 + seg*8] = *(const float4*)(BPl + off);
            }
        } else {
            #pragma unroll
            for (int t = tid; t < 512; t += 256){
                int r = t >> 4, seg = t & 15;
                long off = (long)(kc + r)*ldB + col0 + seg*8;
                *(float4*)&Bs[0][r*136 + seg*8] = *(const float4*)(BPh + off);
                *(float4*)&Bs[1][r*136 + seg*8] = *(const float4*)(BPl + off);
            }
        }
        __syncthreads();

        #pragma unroll
        for (int ks = 0; ks < 2; ks++){
            wmma::fragment<wmma::matrix_a,16,16,16,__nv_bfloat16,wmma::row_major> afh[2], afl[2];
            #pragma unroll
            for (int i = 0; i < 2; i++){
                wmma::load_matrix_sync(afh[i], &As[0][wr*32 + i*16][ks*16], 40);
                wmma::load_matrix_sync(afl[i], &As[1][wr*32 + i*16][ks*16], 40);
            }
            if (TRANSB){
                #pragma unroll
                for (int j = 0; j < 4; j++){
                    wmma::fragment<wmma::matrix_b,16,16,16,__nv_bfloat16,wmma::col_major> bfh, bfl;
                    int nb = wc*64 + j*16;
                    wmma::load_matrix_sync(bfh, &Bs[0][nb*40 + ks*16], 40);
                    wmma::load_matrix_sync(bfl, &Bs[1][nb*40 + ks*16], 40);
                    #pragma unroll
                    for (int i = 0; i < 2; i++){
                        wmma::mma_sync(acc[i][j], afh[i], bfh, acc[i][j]);
                        wmma::mma_sync(acc[i][j], afh[i], bfl, acc[i][j]);
                        wmma::mma_sync(acc[i][j], afl[i], bfh, acc[i][j]);
                    }
                }
            } else {
                #pragma unroll
                for (int j = 0; j < 4; j++){
                    wmma::fragment<wmma::matrix_b,16,16,16,__nv_bfloat16,wmma::row_major> bfh, bfl;
                    int nb = wc*64 + j*16;
                    wmma::load_matrix_sync(bfh, &Bs[0][(ks*16)*136 + nb], 136);
                    wmma::load_matrix_sync(bfl, &Bs[1][(ks*16)*136 + nb], 136);
                    #pragma unroll
                    for (int i = 0; i < 2; i++){
                        wmma::mma_sync(acc[i][j], afh[i], bfh, acc[i][j]);
                        wmma::mma_sync(acc[i][j], afh[i], bfl, acc[i][j]);
                        wmma::mma_sync(acc[i][j], afl[i], bfh, acc[i][j]);
                    }
                }
            }
        }
        __syncthreads();
    }

    // ---- epilogue ----
    if (EPI == 2){
        #pragma unroll
        for (int i = 0; i < 2; i++)
            #pragma unroll
            for (int j = 0; j < 4; j++){
                float* cp = Cb + (row0 + wr*32 + i*16)*(long)N + col0 + wc*64 + j*16;
                wmma::store_matrix_sync(cp, acc[i][j], N, wmma::mem_row_major);
            }
        return;
    }

    // scratch in Bs (free after last sync)
    float* scr = ((float*)Bs) + wid*320;   // 16x20 per warp
    float alpha = (EPI == 1) ? __ldg(alpha_p) : 1.f;
    #pragma unroll
    for (int i = 0; i < 2; i++){
        #pragma unroll
        for (int j = 0; j < 4; j++){
            wmma::store_matrix_sync(scr, acc[i][j], 20, wmma::mem_row_major);
            __syncwarp();
            #pragma unroll
            for (int e = lane; e < 256; e += 32){
                int r = e >> 4, c = e & 15;
                long grow = row0 + wr*32 + i*16 + r;
                long gcol = col0 + wc*64 + j*16 + c;
                float v = scr[r*20 + c] + bias[gcol];
                if (EPI == 0){
                    v = fmaxf(v, 0.f);
                    __nv_bfloat16 h, l;
                    bsplit(v, h, l);
                    g_hidh[grow*OH + gcol] = h;
                    g_hidl[grow*OH + gcol] = l;
                } else {
                    Cb[grow*(long)N + gcol] = v * alpha;
                }
            }
            __syncwarp();
        }
    }
}

// ============================================================
extern "C" void kernel_launch(void* const* d_in, const int* in_sizes, int n_in,
                              void* d_out, int out_size)
{
    const float* Hj   = (const float*)d_in[0];
    const float* Hi   = (const float*)d_in[1];
    const float* mask = (const float*)d_in[2];
    const float* pjw  = (const float*)d_in[3];
    const float* piw  = (const float*)d_in[4];
    const float* sw1  = (const float*)d_in[5];
    const float* sb1  = (const float*)d_in[6];
    const float* sw2  = (const float*)d_in[7];
    const float* sb2  = (const float*)d_in[8];
    const float* vw1  = (const float*)d_in[9];
    const float* vb1  = (const float*)d_in[10];
    const float* vw2  = (const float*)d_in[11];
    const float* vb2  = (const float*)d_in[12];
    const float* alpha= (const float*)d_in[13];
    float* out = (float*)d_out;

    void *pctx, *ppbh, *ppbl, *phih, *phil, *pm1h, *pm1l;
    void *pw1h, *pw1l, *phdh, *phdl, *pw2h, *pw2l;
    cudaGetSymbolAddress(&pctx, g_ctx);
    cudaGetSymbolAddress(&ppbh, g_pbh);  cudaGetSymbolAddress(&ppbl, g_pbl);
    cudaGetSymbolAddress(&phih, g_hih);  cudaGetSymbolAddress(&phil, g_hil);
    cudaGetSymbolAddress(&pm1h, g_m1h);  cudaGetSymbolAddress(&pm1l, g_m1l);
    cudaGetSymbolAddress(&pw1h, g_w1h);  cudaGetSymbolAddress(&pw1l, g_w1l);
    cudaGetSymbolAddress(&phdh, g_hidh); cudaGetSymbolAddress(&phdl, g_hidl);
    cudaGetSymbolAddress(&pw2h, g_w2h);  cudaGetSymbolAddress(&pw2l, g_w2l);

    // 0
    proj_kernel<<<NROWS, 256>>>(Hj, Hi, pjw, piw, sw1);
    // 1: Hi -> bf16 hi/lo
    conv_split<<<(NROWS*Hh/4 + 255)/256, 256>>>(Hi, (__nv_bfloat16*)phih,
                                                (__nv_bfloat16*)phil, NROWS*Hh/4);
    // 2: vw1 -> bf16 hi/lo
    conv_split<<<(OH*H3/4 + 255)/256, 256>>>(vw1, (__nv_bfloat16*)pw1h,
                                             (__nv_bfloat16*)pw1l, OH*H3/4);
    // 3: pair (profiled slot)
    pair_kernel<<<NROWS, 256>>>(sw1, sb1, sw2, sb2, mask);
    // 4: ctx = probs @ Hi  [NN, batched, EPI2 raw fp32]
    {
        dim3 g(Hh/128, Ss/128, Bb);
        gemm_wmma<false,2><<<g, 256>>>(
            (const __nv_bfloat16*)ppbh, (const __nv_bfloat16*)ppbl,
            (const __nv_bfloat16*)phih, (const __nv_bfloat16*)phil,
            (float*)pctx, Hh, Ss, Ss, Hh,
            (long)Ss*Ss, (long)Ss*Hh, (long)Ss*Hh, nullptr, nullptr);
    }
    // 5: msg_in -> bf16 hi/lo
    msgin_conv<<<(NROWS*(Hh/4) + 255)/256, 256>>>(Hj);
    // 6: hid = relu(msg_in @ vw1^T + vb1)  [NT, EPI0]
    {
        dim3 g(OH/128, NROWS/128, 1);
        gemm_wmma<true,0><<<g, 256>>>(
            (const __nv_bfloat16*)pm1h, (const __nv_bfloat16*)pm1l,
            (const __nv_bfloat16*)pw1h, (const __nv_bfloat16*)pw1l,
            nullptr, OH, H3, H3, H3,
            0, 0, 0, vb1, nullptr);
    }
    // 7: vw2 -> bf16 hi/lo
    conv_split<<<(Hh*OH/4 + 255)/256, 256>>>(vw2, (__nv_bfloat16*)pw2h,
                                             (__nv_bfloat16*)pw2l, Hh*OH/4);
    // 8: out = alpha * (hid @ vw2^T + vb2)  [NT, EPI1]
    {
        dim3 g(Hh/128, NROWS/128, 1);
        gemm_wmma<true,1><<<g, 256>>>(
            (const __nv_bfloat16*)phdh, (const __nv_bfloat16*)phdl,
            (const __nv_bfloat16*)pw2h, (const __nv_bfloat16*)pw2l,
            out, Hh, OH, OH, OH,
            0, 0, 0, vb2, alpha);
    }
    (void)in_sizes; (void)n_in; (void)out_size;
}

// round 6
// speedup vs baseline: 1.3984x; 1.3984x over previous
#include <cuda_runtime.h>
#include <cuda_bf16.h>
#include <mma.h>
#include <math.h>
#include <cstdint>

using namespace nvcuda;

#define Bb 4
#define Ss 512
#define Hh 768
#define Dd 24
#define Mm 96
#define OH 768
#define H3 2304
#define NROWS (Bb*Ss)   // 2048

typedef unsigned long long ull;

// ---- scratch ----
__device__ __align__(16) float g_Zj[NROWS*Dd];
__device__ __align__(16) float g_Zi[NROWS*Dd];
__device__ __align__(16) float g_Aj[NROWS*Mm];
__device__ __align__(16) float g_ctx[(long)NROWS*Hh];
// bf16 hi/lo operands for tensor-core GEMMs
__device__ __align__(16) __nv_bfloat16 g_pbh[(long)Bb*Ss*Ss];
__device__ __align__(16) __nv_bfloat16 g_pbl[(long)Bb*Ss*Ss];
__device__ __align__(16) __nv_bfloat16 g_hih[(long)NROWS*Hh];
__device__ __align__(16) __nv_bfloat16 g_hil[(long)NROWS*Hh];
__device__ __align__(16) __nv_bfloat16 g_m1h[(long)NROWS*H3];
__device__ __align__(16) __nv_bfloat16 g_m1l[(long)NROWS*H3];
__device__ __align__(16) __nv_bfloat16 g_w1h[(long)OH*H3];
__device__ __align__(16) __nv_bfloat16 g_w1l[(long)OH*H3];
__device__ __align__(16) __nv_bfloat16 g_hidh[(long)NROWS*OH];
__device__ __align__(16) __nv_bfloat16 g_hidl[(long)NROWS*OH];
__device__ __align__(16) __nv_bfloat16 g_w2h[(long)Hh*OH];
__device__ __align__(16) __nv_bfloat16 g_w2l[(long)Hh*OH];

// bf16 hi/lo split
__device__ __forceinline__ void bsplit(float v, __nv_bfloat16& h, __nv_bfloat16& l){
    h = __float2bfloat16(v);
    l = __float2bfloat16(v - __bfloat162float(h));
}

// ============================================================
// K1: projections + rank-1 term Aj = Wa @ zj
// ============================================================
__global__ __launch_bounds__(256) void proj_kernel(
    const float* __restrict__ Hj, const float* __restrict__ Hi,
    const float* __restrict__ pjw, const float* __restrict__ piw,
    const float* __restrict__ sw1)
{
    int r = blockIdx.x;
    __shared__ float shj[Hh], shi[Hh], szj[Dd];
    int tid = threadIdx.x;
    for (int i = tid; i < Hh; i += 256){
        shj[i] = Hj[(long)r*Hh + i];
        shi[i] = Hi[(long)r*Hh + i];
    }
    __syncthreads();
    int o = tid >> 3, g = tid & 7;
    if (o < Dd){
        float pj = 0.f, pi = 0.f;
        for (int h = g; h < Hh; h += 8){
            pj += shj[h] * pjw[o*Hh + h];
            pi += shi[h] * piw[o*Hh + h];
        }
        #pragma unroll
        for (int d = 4; d > 0; d >>= 1){
            pj += __shfl_down_sync(0xffffffffu, pj, d, 8);
            pi += __shfl_down_sync(0xffffffffu, pi, d, 8);
        }
        if (g == 0){
            szj[o] = pj;
            g_Zj[r*Dd + o] = pj; g_Zi[r*Dd + o] = pi;
        }
    }
    __syncthreads();
    if (tid < Mm){
        float a = 0.f;
        #pragma unroll
        for (int d = 0; d < Dd; d++)
            a += sw1[tid*96 + d] * szj[d];
        g_Aj[r*Mm + tid] = a;
    }
}

// ============================================================
// K2: pair logits as WMMA GEMM + fused softmax.
// Per CTA r=(b,s): F[t, 80] = [zj*zi | |zj-zi| | zi | 0],
// W'[96][80] = [Wc | Wd | Wb | 0]; hid = F @ W'^T (bf16 hi/lo, 3-pass),
// logits[t] = sum_m w2[m]*relu(hid[t,m] + Aj[m]+sb1[m]); softmax -> probs.
// ============================================================
#define PAIR_SMEM 178176
__global__ __launch_bounds__(256) void pair_wmma(
    const float* __restrict__ sw1, const float* __restrict__ sb1,
    const float* __restrict__ sw2v, const float* __restrict__ sb2,
    const float* __restrict__ mask)
{
    extern __shared__ char ps[];
    __nv_bfloat16* Fh = (__nv_bfloat16*)(ps);            // [256][88]
    __nv_bfloat16* Fl = (__nv_bfloat16*)(ps + 45056);    // [256][88]
    __nv_bfloat16* Wh = (__nv_bfloat16*)(ps + 90112);    // [96][88]
    __nv_bfloat16* Wl = (__nv_bfloat16*)(ps + 107008);   // [96][88]
    float* scr  = (float*)(ps + 123904);                 // [8][16][100]
    float* slog = (float*)(ps + 175104);                 // [512]
    float* szj  = (float*)(ps + 177152);                 // [24]
    float* ssc  = (float*)(ps + 177280);                 // [96]
    float* sw2s = (float*)(ps + 177664);                 // [96]
    float* sred = (float*)(ps + 178048);                 // [8]

    int r = blockIdx.x, b = r >> 9;
    int tid = threadIdx.x, wid = tid >> 5, lane = tid & 31;

    // build W' = [Wc | Wd | Wb | 0], bf16 hi/lo
    for (int i = tid; i < 96*88; i += 256){
        int m = i / 88, k = i % 88;
        float wv = 0.f;
        if (k < 24)      wv = sw1[m*96 + 48 + k];
        else if (k < 48) wv = sw1[m*96 + 72 + (k-24)];
        else if (k < 72) wv = sw1[m*96 + 24 + (k-48)];
        __nv_bfloat16 h, l; bsplit(wv, h, l);
        Wh[i] = h; Wl[i] = l;
    }
    if (tid < Dd) szj[tid] = g_Zj[r*Dd + tid];
    if (tid < Mm){
        ssc[tid]  = g_Aj[r*Mm + tid] + sb1[tid];
        sw2s[tid] = sw2v[tid];
    }
    __syncthreads();

    #pragma unroll 1
    for (int chunk = 0; chunk < 2; chunk++){
        // ---- build F for t in [chunk*256, chunk*256+256) ----
        {
            int t = chunk*256 + tid;
            const float* zi = &g_Zi[(long)(b*Ss + t)*Dd];
            __nv_bfloat16* fh = &Fh[tid*88];
            __nv_bfloat16* fl = &Fl[tid*88];
            #pragma unroll
            for (int d = 0; d < Dd; d++){
                float z = __ldg(&zi[d]), zj = szj[d];
                __nv_bfloat16 h, l;
                bsplit(zj*z, h, l);        fh[d]    = h; fl[d]    = l;
                bsplit(fabsf(zj-z), h, l); fh[24+d] = h; fl[24+d] = l;
                bsplit(z, h, l);           fh[48+d] = h; fl[48+d] = l;
            }
            __nv_bfloat16 z16 = __float2bfloat16(0.f);
            #pragma unroll
            for (int k = 72; k < 88; k++){ fh[k] = z16; fl[k] = z16; }
        }
        __syncthreads();

        // ---- GEMM: each warp owns 2 t-tiles of 16 rows ----
        #pragma unroll 1
        for (int tt = 0; tt < 2; tt++){
            int ttile = wid*2 + tt;
            wmma::fragment<wmma::accumulator,16,16,16,float> acc[6];
            #pragma unroll
            for (int j = 0; j < 6; j++) wmma::fill_fragment(acc[j], 0.f);

            #pragma unroll
            for (int k = 0; k < 5; k++){
                wmma::fragment<wmma::matrix_a,16,16,16,__nv_bfloat16,wmma::row_major> ah, al;
                wmma::load_matrix_sync(ah, &Fh[(ttile*16)*88 + k*16], 88);
                wmma::load_matrix_sync(al, &Fl[(ttile*16)*88 + k*16], 88);
                #pragma unroll
                for (int j = 0; j < 6; j++){
                    wmma::fragment<wmma::matrix_b,16,16,16,__nv_bfloat16,wmma::col_major> bh, bl;
                    wmma::load_matrix_sync(bh, &Wh[(j*16)*88 + k*16], 88);
                    wmma::load_matrix_sync(bl, &Wl[(j*16)*88 + k*16], 88);
                    wmma::mma_sync(acc[j], ah, bh, acc[j]);
                    wmma::mma_sync(acc[j], ah, bl, acc[j]);
                    wmma::mma_sync(acc[j], al, bh, acc[j]);
                }
            }
            // stash hid tile, then reduce to logits
            float* ws = scr + wid*1600;   // 16 x 100
            #pragma unroll
            for (int j = 0; j < 6; j++)
                wmma::store_matrix_sync(ws + j*16, acc[j], 100, wmma::mem_row_major);
            __syncwarp();

            int row = lane & 15;
            int mh  = (lane >> 4) * 48;
            const float* sr = ws + row*100 + mh;
            float sum = 0.f;
            #pragma unroll
            for (int m = 0; m < 48; m++){
                float v = sr[m] + ssc[mh + m];
                sum += sw2s[mh + m] * fmaxf(v, 0.f);
            }
            sum += __shfl_xor_sync(0xffffffffu, sum, 16);
            if (lane < 16) slog[chunk*256 + ttile*16 + row] = sum;
            __syncwarp();
        }
        __syncthreads();
    }

    // ---- masked softmax over slog[512] ----
    int t0 = tid, t1 = tid + 256;
    float lt0 = slog[t0] + sb2[0] + (1.f - mask[b*Ss + t0]) * (-3.402823466e38f);
    float lt1 = slog[t1] + sb2[0] + (1.f - mask[b*Ss + t1]) * (-3.402823466e38f);

    float mx = fmaxf(lt0, lt1);
    #pragma unroll
    for (int d = 16; d > 0; d >>= 1)
        mx = fmaxf(mx, __shfl_xor_sync(0xffffffffu, mx, d));
    if (lane == 0) sred[wid] = mx;
    __syncthreads();
    float bmax = sred[0];
    #pragma unroll
    for (int i = 1; i < 8; i++) bmax = fmaxf(bmax, sred[i]);

    float e0 = expf(lt0 - bmax);
    float e1 = expf(lt1 - bmax);
    float sm = e0 + e1;
    #pragma unroll
    for (int d = 16; d > 0; d >>= 1)
        sm += __shfl_xor_sync(0xffffffffu, sm, d);
    __syncthreads();
    if (lane == 0) sred[wid] = sm;
    __syncthreads();
    float tot = 0.f;
    #pragma unroll
    for (int i = 0; i < 8; i++) tot += sred[i];
    float inv = 1.f / tot;

    __nv_bfloat16 h, l;
    bsplit(e0 * inv, h, l);
    g_pbh[(long)r*Ss + t0] = h; g_pbl[(long)r*Ss + t0] = l;
    bsplit(e1 * inv, h, l);
    g_pbh[(long)r*Ss + t1] = h; g_pbl[(long)r*Ss + t1] = l;
}

// ============================================================
// K3: fp32 -> bf16 hi/lo split (vectorized)
// ============================================================
__global__ __launch_bounds__(256) void conv_split(
    const float* __restrict__ x, __nv_bfloat16* __restrict__ hi,
    __nv_bfloat16* __restrict__ lo, int n4)
{
    int i = blockIdx.x*256 + threadIdx.x;
    if (i >= n4) return;
    float4 v = ((const float4*)x)[i];
    __nv_bfloat16 h0,h1,h2,h3,l0,l1,l2,l3;
    bsplit(v.x,h0,l0); bsplit(v.y,h1,l1); bsplit(v.z,h2,l2); bsplit(v.w,h3,l3);
    __nv_bfloat162 p0, p1;
    p0.x=h0; p0.y=h1; p1.x=h2; p1.y=h3;
    ((__nv_bfloat162*)hi)[2*i]   = p0;
    ((__nv_bfloat162*)hi)[2*i+1] = p1;
    p0.x=l0; p0.y=l1; p1.x=l2; p1.y=l3;
    ((__nv_bfloat162*)lo)[2*i]   = p0;
    ((__nv_bfloat162*)lo)[2*i+1] = p1;
}

// ============================================================
// K4: msg_in = [ctx | Hj | ctx*Hj] -> bf16 hi/lo
// ============================================================
__device__ __forceinline__ void store4(__nv_bfloat16* hp, __nv_bfloat16* lp,
                                       float a, float b, float c, float d)
{
    __nv_bfloat16 h0,h1,h2,h3,l0,l1,l2,l3;
    bsplit(a,h0,l0); bsplit(b,h1,l1); bsplit(c,h2,l2); bsplit(d,h3,l3);
    __nv_bfloat162 p0, p1;
    p0.x=h0; p0.y=h1; p1.x=h2; p1.y=h3;
    ((__nv_bfloat162*)hp)[0] = p0; ((__nv_bfloat162*)hp)[1] = p1;
    p0.x=l0; p0.y=l1; p1.x=l2; p1.y=l3;
    ((__nv_bfloat162*)lp)[0] = p0; ((__nv_bfloat162*)lp)[1] = p1;
}
__global__ __launch_bounds__(256) void msgin_conv(const float* __restrict__ Hj)
{
    int i = blockIdx.x*256 + threadIdx.x;
    if (i >= NROWS*(Hh/4)) return;
    int r = i / (Hh/4);
    int c = (i % (Hh/4)) * 4;
    float4 cv = *(const float4*)&g_ctx[(long)r*Hh + c];
    float4 hv = *(const float4*)&Hj[(long)r*Hh + c];
    long base = (long)r*H3 + c;
    store4(&g_m1h[base],      &g_m1l[base],      cv.x, cv.y, cv.z, cv.w);
    store4(&g_m1h[base+Hh],   &g_m1l[base+Hh],   hv.x, hv.y, hv.z, hv.w);
    store4(&g_m1h[base+2*Hh], &g_m1l[base+2*Hh],
           cv.x*hv.x, cv.y*hv.y, cv.z*hv.z, cv.w*hv.w);
}

// ============================================================
// K5: WMMA GEMM  C[M,N] = A[M,K] @ opB  (bf16 hi/lo, 3-pass)
// ============================================================
template<bool TRANSB, int EPI>
__global__ __launch_bounds__(256) void gemm_wmma(
    const __nv_bfloat16* __restrict__ Ah, const __nv_bfloat16* __restrict__ Al,
    const __nv_bfloat16* __restrict__ Bh, const __nv_bfloat16* __restrict__ Bl,
    float* __restrict__ Cout, int N, int K, int ldA, int ldB,
    long strideA, long strideB, long strideC,
    const float* __restrict__ bias, const float* __restrict__ alpha_p)
{
    __shared__ __nv_bfloat16 As[2][128][40];
    __shared__ __nv_bfloat16 Bs[2][5120];   // NT: [n][40] ; NN: [k][136]

    int tid = threadIdx.x;
    int wid = tid >> 5, lane = tid & 31;
    int wr = wid & 3, wc = wid >> 2;        // 4x2 warps, warp tile 32x64
    long row0 = (long)blockIdx.y * 128;
    long col0 = (long)blockIdx.x * 128;

    const __nv_bfloat16* APh = Ah + (long)blockIdx.z * strideA;
    const __nv_bfloat16* APl = Al + (long)blockIdx.z * strideA;
    const __nv_bfloat16* BPh = Bh + (long)blockIdx.z * strideB;
    const __nv_bfloat16* BPl = Bl + (long)blockIdx.z * strideB;
    float* Cb = Cout ? (Cout + (long)blockIdx.z * strideC) : nullptr;

    wmma::fragment<wmma::accumulator,16,16,16,float> acc[2][4];
    #pragma unroll
    for (int i = 0; i < 2; i++)
        #pragma unroll
        for (int j = 0; j < 4; j++) wmma::fill_fragment(acc[i][j], 0.f);

    #pragma unroll 1
    for (int kc = 0; kc < K; kc += 32){
        #pragma unroll
        for (int t = tid; t < 512; t += 256){
            int r = t >> 2, seg = t & 3;
            long off = (row0 + r)*(long)ldA + kc + seg*8;
            *(float4*)&As[0][r][seg*8] = *(const float4*)(APh + off);
            *(float4*)&As[1][r][seg*8] = *(const float4*)(APl + off);
        }
        if (TRANSB){
            #pragma unroll
            for (int t = tid; t < 512; t += 256){
                int r = t >> 2, seg = t & 3;
                long off = (col0 + r)*(long)ldB + kc + seg*8;
                *(float4*)&Bs[0][r*40 + seg*8] = *(const float4*)(BPh + off);
                *(float4*)&Bs[1][r*40 + seg*8] = *(const float4*)(BPl + off);
            }
        } else {
            #pragma unroll
            for (int t = tid; t < 512; t += 256){
                int r = t >> 4, seg = t & 15;
                long off = (long)(kc + r)*ldB + col0 + seg*8;
                *(float4*)&Bs[0][r*136 + seg*8] = *(const float4*)(BPh + off);
                *(float4*)&Bs[1][r*136 + seg*8] = *(const float4*)(BPl + off);
            }
        }
        __syncthreads();

        #pragma unroll
        for (int ks = 0; ks < 2; ks++){
            wmma::fragment<wmma::matrix_a,16,16,16,__nv_bfloat16,wmma::row_major> afh[2], afl[2];
            #pragma unroll
            for (int i = 0; i < 2; i++){
                wmma::load_matrix_sync(afh[i], &As[0][wr*32 + i*16][ks*16], 40);
                wmma::load_matrix_sync(afl[i], &As[1][wr*32 + i*16][ks*16], 40);
            }
            if (TRANSB){
                #pragma unroll
                for (int j = 0; j < 4; j++){
                    wmma::fragment<wmma::matrix_b,16,16,16,__nv_bfloat16,wmma::col_major> bfh, bfl;
                    int nb = wc*64 + j*16;
                    wmma::load_matrix_sync(bfh, &Bs[0][nb*40 + ks*16], 40);
                    wmma::load_matrix_sync(bfl, &Bs[1][nb*40 + ks*16], 40);
                    #pragma unroll
                    for (int i = 0; i < 2; i++){
                        wmma::mma_sync(acc[i][j], afh[i], bfh, acc[i][j]);
                        wmma::mma_sync(acc[i][j], afh[i], bfl, acc[i][j]);
                        wmma::mma_sync(acc[i][j], afl[i], bfh, acc[i][j]);
                    }
                }
            } else {
                #pragma unroll
                for (int j = 0; j < 4; j++){
                    wmma::fragment<wmma::matrix_b,16,16,16,__nv_bfloat16,wmma::row_major> bfh, bfl;
                    int nb = wc*64 + j*16;
                    wmma::load_matrix_sync(bfh, &Bs[0][(ks*16)*136 + nb], 136);
                    wmma::load_matrix_sync(bfl, &Bs[1][(ks*16)*136 + nb], 136);
                    #pragma unroll
                    for (int i = 0; i < 2; i++){
                        wmma::mma_sync(acc[i][j], afh[i], bfh, acc[i][j]);
                        wmma::mma_sync(acc[i][j], afh[i], bfl, acc[i][j]);
                        wmma::mma_sync(acc[i][j], afl[i], bfh, acc[i][j]);
                    }
                }
            }
        }
        __syncthreads();
    }

    if (EPI == 2){
        #pragma unroll
        for (int i = 0; i < 2; i++)
            #pragma unroll
            for (int j = 0; j < 4; j++){
                float* cp = Cb + (row0 + wr*32 + i*16)*(long)N + col0 + wc*64 + j*16;
                wmma::store_matrix_sync(cp, acc[i][j], N, wmma::mem_row_major);
            }
        return;
    }

    float* scr = ((float*)Bs) + wid*320;   // 16x20 per warp
    float alpha = (EPI == 1) ? __ldg(alpha_p) : 1.f;
    #pragma unroll
    for (int i = 0; i < 2; i++){
        #pragma unroll
        for (int j = 0; j < 4; j++){
            wmma::store_matrix_sync(scr, acc[i][j], 20, wmma::mem_row_major);
            __syncwarp();
            #pragma unroll
            for (int e = lane; e < 256; e += 32){
                int r = e >> 4, c = e & 15;
                long grow = row0 + wr*32 + i*16 + r;
                long gcol = col0 + wc*64 + j*16 + c;
                float v = scr[r*20 + c] + bias[gcol];
                if (EPI == 0){
                    v = fmaxf(v, 0.f);
                    __nv_bfloat16 h, l;
                    bsplit(v, h, l);
                    g_hidh[grow*OH + gcol] = h;
                    g_hidl[grow*OH + gcol] = l;
                } else {
                    Cb[grow*(long)N + gcol] = v * alpha;
                }
            }
            __syncwarp();
        }
    }
}

// ============================================================
extern "C" void kernel_launch(void* const* d_in, const int* in_sizes, int n_in,
                              void* d_out, int out_size)
{
    const float* Hj   = (const float*)d_in[0];
    const float* Hi   = (const float*)d_in[1];
    const float* mask = (const float*)d_in[2];
    const float* pjw  = (const float*)d_in[3];
    const float* piw  = (const float*)d_in[4];
    const float* sw1  = (const float*)d_in[5];
    const float* sb1  = (const float*)d_in[6];
    const float* sw2  = (const float*)d_in[7];
    const float* sb2  = (const float*)d_in[8];
    const float* vw1  = (const float*)d_in[9];
    const float* vb1  = (const float*)d_in[10];
    const float* vw2  = (const float*)d_in[11];
    const float* vb2  = (const float*)d_in[12];
    const float* alpha= (const float*)d_in[13];
    float* out = (float*)d_out;

    void *pctx, *ppbh, *ppbl, *phih, *phil, *pm1h, *pm1l;
    void *pw1h, *pw1l, *phdh, *phdl, *pw2h, *pw2l;
    cudaGetSymbolAddress(&pctx, g_ctx);
    cudaGetSymbolAddress(&ppbh, g_pbh);  cudaGetSymbolAddress(&ppbl, g_pbl);
    cudaGetSymbolAddress(&phih, g_hih);  cudaGetSymbolAddress(&phil, g_hil);
    cudaGetSymbolAddress(&pm1h, g_m1h);  cudaGetSymbolAddress(&pm1l, g_m1l);
    cudaGetSymbolAddress(&pw1h, g_w1h);  cudaGetSymbolAddress(&pw1l, g_w1l);
    cudaGetSymbolAddress(&phdh, g_hidh); cudaGetSymbolAddress(&phdl, g_hidl);
    cudaGetSymbolAddress(&pw2h, g_w2h);  cudaGetSymbolAddress(&pw2l, g_w2l);

    cudaFuncSetAttribute(pair_wmma, cudaFuncAttributeMaxDynamicSharedMemorySize, PAIR_SMEM);

    // 1
    proj_kernel<<<NROWS, 256>>>(Hj, Hi, pjw, piw, sw1);
    // 2: Hi -> bf16 hi/lo
    conv_split<<<(NROWS*Hh/4 + 255)/256, 256>>>(Hi, (__nv_bfloat16*)phih,
                                                (__nv_bfloat16*)phil, NROWS*Hh/4);
    // 3: vw1 -> bf16 hi/lo
    conv_split<<<(OH*H3/4 + 255)/256, 256>>>(vw1, (__nv_bfloat16*)pw1h,
                                             (__nv_bfloat16*)pw1l, OH*H3/4);
    // 4: pair (profiled slot)
    pair_wmma<<<NROWS, 256, PAIR_SMEM>>>(sw1, sb1, sw2, sb2, mask);
    // 5: ctx = probs @ Hi  [NN, batched, EPI2 raw fp32]
    {
        dim3 g(Hh/128, Ss/128, Bb);
        gemm_wmma<false,2><<<g, 256>>>(
            (const __nv_bfloat16*)ppbh, (const __nv_bfloat16*)ppbl,
            (const __nv_bfloat16*)phih, (const __nv_bfloat16*)phil,
            (float*)pctx, Hh, Ss, Ss, Hh,
            (long)Ss*Ss, (long)Ss*Hh, (long)Ss*Hh, nullptr, nullptr);
    }
    // 6: msg_in -> bf16 hi/lo
    msgin_conv<<<(NROWS*(Hh/4) + 255)/256, 256>>>(Hj);
    // 7: hid = relu(msg_in @ vw1^T + vb1)  [NT, EPI0]
    {
        dim3 g(OH/128, NROWS/128, 1);
        gemm_wmma<true,0><<<g, 256>>>(
            (const __nv_bfloat16*)pm1h, (const __nv_bfloat16*)pm1l,
            (const __nv_bfloat16*)pw1h, (const __nv_bfloat16*)pw1l,
            nullptr, OH, H3, H3, H3,
            0, 0, 0, vb1, nullptr);
    }
    // 8: vw2 -> bf16 hi/lo
    conv_split<<<(Hh*OH/4 + 255)/256, 256>>>(vw2, (__nv_bfloat16*)pw2h,
                                             (__nv_bfloat16*)pw2l, Hh*OH/4);
    // 9: out = alpha * (hid @ vw2^T + vb2)  [NT, EPI1]
    {
        dim3 g(Hh/128, NROWS/128, 1);
        gemm_wmma<true,1><<<g, 256>>>(
            (const __nv_bfloat16*)phdh, (const __nv_bfloat16*)phdl,
            (const __nv_bfloat16*)pw2h, (const __nv_bfloat16*)pw2l,
            out, Hh, OH, OH, OH,
            0, 0, 0, vb2, alpha);
    }
    (void)in_sizes; (void)n_in; (void)out_size;
}

// round 7
// speedup vs baseline: 1.6366x; 1.1704x over previous
#include <cuda_runtime.h>
#include <cuda_bf16.h>
#include <mma.h>
#include <math.h>
#include <cstdint>

using namespace nvcuda;

#define Bb 4
#define Ss 512
#define Hh 768
#define Dd 24
#define Mm 96
#define OH 768
#define H3 2304
#define NROWS (Bb*Ss)   // 2048

typedef unsigned long long ull;

// ---- scratch ----
__device__ __align__(16) float g_Zj[NROWS*Dd];
__device__ __align__(16) float g_Zi[NROWS*Dd];
__device__ __align__(16) float g_Aj[NROWS*Mm];
__device__ __align__(16) float g_ctx[(long)NROWS*Hh];
// precomputed pair weight matrix W' = [Wc | Wd | Wb | 0]  (96 x 80, hi/lo)
__device__ __align__(16) __nv_bfloat16 g_Wph[96*80];
__device__ __align__(16) __nv_bfloat16 g_Wpl[96*80];
// bf16 hi/lo operands for tensor-core GEMMs
__device__ __align__(16) __nv_bfloat16 g_pbh[(long)Bb*Ss*Ss];
__device__ __align__(16) __nv_bfloat16 g_pbl[(long)Bb*Ss*Ss];
__device__ __align__(16) __nv_bfloat16 g_hih[(long)NROWS*Hh];
__device__ __align__(16) __nv_bfloat16 g_hil[(long)NROWS*Hh];
__device__ __align__(16) __nv_bfloat16 g_m1h[(long)NROWS*H3];
__device__ __align__(16) __nv_bfloat16 g_m1l[(long)NROWS*H3];
__device__ __align__(16) __nv_bfloat16 g_w1h[(long)OH*H3];
__device__ __align__(16) __nv_bfloat16 g_w1l[(long)OH*H3];
__device__ __align__(16) __nv_bfloat16 g_hidh[(long)NROWS*OH];
__device__ __align__(16) __nv_bfloat16 g_hidl[(long)NROWS*OH];
__device__ __align__(16) __nv_bfloat16 g_w2h[(long)Hh*OH];
__device__ __align__(16) __nv_bfloat16 g_w2l[(long)Hh*OH];

// bf16 hi/lo split
__device__ __forceinline__ void bsplit(float v, __nv_bfloat16& h, __nv_bfloat16& l){
    h = __float2bfloat16(v);
    l = __float2bfloat16(v - __bfloat162float(h));
}

// ============================================================
// K0: precompute W' = [Wc | Wd | Wb | 0] (96 x 80) hi/lo
// ============================================================
__global__ __launch_bounds__(256) void wsplit_pair(const float* __restrict__ sw1)
{
    int i = blockIdx.x*256 + threadIdx.x;
    if (i >= 96*80) return;
    int m = i / 80, k = i % 80;
    float wv = 0.f;
    if (k < 24)      wv = sw1[m*96 + 48 + k];
    else if (k < 48) wv = sw1[m*96 + 72 + (k-24)];
    else if (k < 72) wv = sw1[m*96 + 24 + (k-48)];
    __nv_bfloat16 h, l; bsplit(wv, h, l);
    g_Wph[i] = h; g_Wpl[i] = l;
}

// ============================================================
// K1: projections + rank-1 term Aj = Wa @ zj
// ============================================================
__global__ __launch_bounds__(256) void proj_kernel(
    const float* __restrict__ Hj, const float* __restrict__ Hi,
    const float* __restrict__ pjw, const float* __restrict__ piw,
    const float* __restrict__ sw1)
{
    int r = blockIdx.x;
    __shared__ float shj[Hh], shi[Hh], szj[Dd];
    int tid = threadIdx.x;
    for (int i = tid; i < Hh; i += 256){
        shj[i] = Hj[(long)r*Hh + i];
        shi[i] = Hi[(long)r*Hh + i];
    }
    __syncthreads();
    int o = tid >> 3, g = tid & 7;
    if (o < Dd){
        float pj = 0.f, pi = 0.f;
        for (int h = g; h < Hh; h += 8){
            pj += shj[h] * pjw[o*Hh + h];
            pi += shi[h] * piw[o*Hh + h];
        }
        #pragma unroll
        for (int d = 4; d > 0; d >>= 1){
            pj += __shfl_down_sync(0xffffffffu, pj, d, 8);
            pi += __shfl_down_sync(0xffffffffu, pi, d, 8);
        }
        if (g == 0){
            szj[o] = pj;
            g_Zj[r*Dd + o] = pj; g_Zi[r*Dd + o] = pi;
        }
    }
    __syncthreads();
    if (tid < Mm){
        float a = 0.f;
        #pragma unroll
        for (int d = 0; d < Dd; d++)
            a += sw1[tid*96 + d] * szj[d];
        g_Aj[r*Mm + tid] = a;
    }
}

// ============================================================
// K2: pair logits as WMMA GEMM + fused softmax (2 CTA/SM version)
// chunk = 128 t-rows; F[128][80]; W' preloaded from global.
// ============================================================
#define OFF_FH   0
#define OFF_FL   20480
#define OFF_WH   40960
#define OFF_WL   56320
#define OFF_SCR  71680      // 8 warps x 16 x 52 floats = 26624
#define OFF_SLOG 98304      // 512 floats
#define OFF_SZJ  100352     // 24 floats (pad 128B)
#define OFF_SSC  100480     // 96 floats
#define OFF_SW2  100864     // 96 floats
#define OFF_SRED 101248     // 8 floats
#define PAIR_SMEM 101376

__global__ __launch_bounds__(256) void pair_wmma(
    const float* __restrict__ sb1,
    const float* __restrict__ sw2v, const float* __restrict__ sb2,
    const float* __restrict__ mask)
{
    extern __shared__ char ps[];
    __nv_bfloat16* Fh = (__nv_bfloat16*)(ps + OFF_FH);
    __nv_bfloat16* Fl = (__nv_bfloat16*)(ps + OFF_FL);
    __nv_bfloat16* Wh = (__nv_bfloat16*)(ps + OFF_WH);
    __nv_bfloat16* Wl = (__nv_bfloat16*)(ps + OFF_WL);
    float* scr  = (float*)(ps + OFF_SCR);
    float* slog = (float*)(ps + OFF_SLOG);
    float* szj  = (float*)(ps + OFF_SZJ);
    float* ssc  = (float*)(ps + OFF_SSC);
    float* sw2s = (float*)(ps + OFF_SW2);
    float* sred = (float*)(ps + OFF_SRED);

    int r = blockIdx.x, b = r >> 9;
    int tid = threadIdx.x, wid = tid >> 5, lane = tid & 31;

    // load precomputed W' (960 uint4 each)
    for (int i = tid; i < 960; i += 256){
        ((uint4*)Wh)[i] = ((const uint4*)g_Wph)[i];
        ((uint4*)Wl)[i] = ((const uint4*)g_Wpl)[i];
    }
    if (tid < Dd) szj[tid] = g_Zj[r*Dd + tid];
    if (tid < Mm){
        ssc[tid]  = g_Aj[r*Mm + tid] + sb1[tid];
        sw2s[tid] = sw2v[tid];
    }
    __syncthreads();

    #pragma unroll 1
    for (int chunk = 0; chunk < 4; chunk++){
        // ---- build F for t in [chunk*128, chunk*128+128) ----
        {
            int row = tid >> 1, half = tid & 1;
            int t = chunk*128 + row;
            const float* zi = &g_Zi[(long)(b*Ss + t)*Dd];
            __nv_bfloat16* fh = &Fh[row*80];
            __nv_bfloat16* fl = &Fl[row*80];
            #pragma unroll
            for (int d = 0; d < 12; d++){
                int idx = half*12 + d;
                float z = __ldg(&zi[idx]), zj = szj[idx];
                __nv_bfloat16 h, l;
                bsplit(zj*z, h, l);        fh[idx]    = h; fl[idx]    = l;
                bsplit(fabsf(zj-z), h, l); fh[24+idx] = h; fl[24+idx] = l;
                bsplit(z, h, l);           fh[48+idx] = h; fl[48+idx] = l;
            }
            __nv_bfloat16 z16 = __float2bfloat16(0.f);
            #pragma unroll
            for (int k = 0; k < 4; k++){
                int idx = 72 + half*4 + k;
                fh[idx] = z16; fl[idx] = z16;
            }
        }
        __syncthreads();

        // ---- GEMM: each warp owns one 16-row t-tile ----
        wmma::fragment<wmma::accumulator,16,16,16,float> acc[6];
        #pragma unroll
        for (int j = 0; j < 6; j++) wmma::fill_fragment(acc[j], 0.f);

        #pragma unroll
        for (int k = 0; k < 5; k++){
            wmma::fragment<wmma::matrix_a,16,16,16,__nv_bfloat16,wmma::row_major> ah, al;
            wmma::load_matrix_sync(ah, &Fh[(wid*16)*80 + k*16], 80);
            wmma::load_matrix_sync(al, &Fl[(wid*16)*80 + k*16], 80);
            #pragma unroll
            for (int j = 0; j < 6; j++){
                wmma::fragment<wmma::matrix_b,16,16,16,__nv_bfloat16,wmma::col_major> bh, bl;
                wmma::load_matrix_sync(bh, &Wh[(j*16)*80 + k*16], 80);
                wmma::load_matrix_sync(bl, &Wl[(j*16)*80 + k*16], 80);
                wmma::mma_sync(acc[j], ah, bh, acc[j]);
                wmma::mma_sync(acc[j], ah, bl, acc[j]);
                wmma::mma_sync(acc[j], al, bh, acc[j]);
            }
        }

        // ---- reduce to logits, two 48-col passes ----
        float* scrw = scr + wid*832;   // 16 x 52 floats
        int row = lane >> 1, sub = lane & 1;
        float lsum = 0.f;
        #pragma unroll
        for (int g = 0; g < 2; g++){
            #pragma unroll
            for (int j = 0; j < 3; j++)
                wmma::store_matrix_sync(scrw + j*16, acc[g*3 + j], 52, wmma::mem_row_major);
            __syncwarp();
            const float* sr = scrw + row*52 + sub*24;
            int mbase = g*48 + sub*24;
            #pragma unroll
            for (int mm = 0; mm < 24; mm++){
                float v = sr[mm] + ssc[mbase + mm];
                lsum += sw2s[mbase + mm] * fmaxf(v, 0.f);
            }
            __syncwarp();
        }
        lsum += __shfl_xor_sync(0xffffffffu, lsum, 1);
        if (sub == 0) slog[chunk*128 + wid*16 + row] = lsum;
        __syncthreads();
    }

    // ---- masked softmax over slog[512] ----
    int t0 = tid, t1 = tid + 256;
    float lt0 = slog[t0] + sb2[0] + (1.f - mask[b*Ss + t0]) * (-3.402823466e38f);
    float lt1 = slog[t1] + sb2[0] + (1.f - mask[b*Ss + t1]) * (-3.402823466e38f);

    float mx = fmaxf(lt0, lt1);
    #pragma unroll
    for (int d = 16; d > 0; d >>= 1)
        mx = fmaxf(mx, __shfl_xor_sync(0xffffffffu, mx, d));
    if (lane == 0) sred[wid] = mx;
    __syncthreads();
    float bmax = sred[0];
    #pragma unroll
    for (int i = 1; i < 8; i++) bmax = fmaxf(bmax, sred[i]);

    float e0 = expf(lt0 - bmax);
    float e1 = expf(lt1 - bmax);
    float sm = e0 + e1;
    #pragma unroll
    for (int d = 16; d > 0; d >>= 1)
        sm += __shfl_xor_sync(0xffffffffu, sm, d);
    __syncthreads();
    if (lane == 0) sred[wid] = sm;
    __syncthreads();
    float tot = 0.f;
    #pragma unroll
    for (int i = 0; i < 8; i++) tot += sred[i];
    float inv = 1.f / tot;

    __nv_bfloat16 h, l;
    bsplit(e0 * inv, h, l);
    g_pbh[(long)r*Ss + t0] = h; g_pbl[(long)r*Ss + t0] = l;
    bsplit(e1 * inv, h, l);
    g_pbh[(long)r*Ss + t1] = h; g_pbl[(long)r*Ss + t1] = l;
}

// ============================================================
// K3: fp32 -> bf16 hi/lo split (vectorized)
// ============================================================
__global__ __launch_bounds__(256) void conv_split(
    const float* __restrict__ x, __nv_bfloat16* __restrict__ hi,
    __nv_bfloat16* __restrict__ lo, int n4)
{
    int i = blockIdx.x*256 + threadIdx.x;
    if (i >= n4) return;
    float4 v = ((const float4*)x)[i];
    __nv_bfloat16 h0,h1,h2,h3,l0,l1,l2,l3;
    bsplit(v.x,h0,l0); bsplit(v.y,h1,l1); bsplit(v.z,h2,l2); bsplit(v.w,h3,l3);
    __nv_bfloat162 p0, p1;
    p0.x=h0; p0.y=h1; p1.x=h2; p1.y=h3;
    ((__nv_bfloat162*)hi)[2*i]   = p0;
    ((__nv_bfloat162*)hi)[2*i+1] = p1;
    p0.x=l0; p0.y=l1; p1.x=l2; p1.y=l3;
    ((__nv_bfloat162*)lo)[2*i]   = p0;
    ((__nv_bfloat162*)lo)[2*i+1] = p1;
}

// ============================================================
// K4: msg_in = [ctx | Hj | ctx*Hj] -> bf16 hi/lo
// ============================================================
__device__ __forceinline__ void store4(__nv_bfloat16* hp, __nv_bfloat16* lp,
                                       float a, float b, float c, float d)
{
    __nv_bfloat16 h0,h1,h2,h3,l0,l1,l2,l3;
    bsplit(a,h0,l0); bsplit(b,h1,l1); bsplit(c,h2,l2); bsplit(d,h3,l3);
    __nv_bfloat162 p0, p1;
    p0.x=h0; p0.y=h1; p1.x=h2; p1.y=h3;
    ((__nv_bfloat162*)hp)[0] = p0; ((__nv_bfloat162*)hp)[1] = p1;
    p0.x=l0; p0.y=l1; p1.x=l2; p1.y=l3;
    ((__nv_bfloat162*)lp)[0] = p0; ((__nv_bfloat162*)lp)[1] = p1;
}
__global__ __launch_bounds__(256) void msgin_conv(const float* __restrict__ Hj)
{
    int i = blockIdx.x*256 + threadIdx.x;
    if (i >= NROWS*(Hh/4)) return;
    int r = i / (Hh/4);
    int c = (i % (Hh/4)) * 4;
    float4 cv = *(const float4*)&g_ctx[(long)r*Hh + c];
    float4 hv = *(const float4*)&Hj[(long)r*Hh + c];
    long base = (long)r*H3 + c;
    store4(&g_m1h[base],      &g_m1l[base],      cv.x, cv.y, cv.z, cv.w);
    store4(&g_m1h[base+Hh],   &g_m1l[base+Hh],   hv.x, hv.y, hv.z, hv.w);
    store4(&g_m1h[base+2*Hh], &g_m1l[base+2*Hh],
           cv.x*hv.x, cv.y*hv.y, cv.z*hv.z, cv.w*hv.w);
}

// ============================================================
// K5: WMMA GEMM  C[M,N] = A[M,K] @ opB  (bf16 hi/lo, 3-pass)
// ============================================================
template<bool TRANSB, int EPI>
__global__ __launch_bounds__(256) void gemm_wmma(
    const __nv_bfloat16* __restrict__ Ah, const __nv_bfloat16* __restrict__ Al,
    const __nv_bfloat16* __restrict__ Bh, const __nv_bfloat16* __restrict__ Bl,
    float* __restrict__ Cout, int N, int K, int ldA, int ldB,
    long strideA, long strideB, long strideC,
    const float* __restrict__ bias, const float* __restrict__ alpha_p)
{
    __shared__ __nv_bfloat16 As[2][128][40];
    __shared__ __nv_bfloat16 Bs[2][5120];   // NT: [n][40] ; NN: [k][136]

    int tid = threadIdx.x;
    int wid = tid >> 5, lane = tid & 31;
    int wr = wid & 3, wc = wid >> 2;        // 4x2 warps, warp tile 32x64
    long row0 = (long)blockIdx.y * 128;
    long col0 = (long)blockIdx.x * 128;

    const __nv_bfloat16* APh = Ah + (long)blockIdx.z * strideA;
    const __nv_bfloat16* APl = Al + (long)blockIdx.z * strideA;
    const __nv_bfloat16* BPh = Bh + (long)blockIdx.z * strideB;
    const __nv_bfloat16* BPl = Bl + (long)blockIdx.z * strideB;
    float* Cb = Cout ? (Cout + (long)blockIdx.z * strideC) : nullptr;

    wmma::fragment<wmma::accumulator,16,16,16,float> acc[2][4];
    #pragma unroll
    for (int i = 0; i < 2; i++)
        #pragma unroll
        for (int j = 0; j < 4; j++) wmma::fill_fragment(acc[i][j], 0.f);

    #pragma unroll 1
    for (int kc = 0; kc < K; kc += 32){
        #pragma unroll
        for (int t = tid; t < 512; t += 256){
            int r = t >> 2, seg = t & 3;
            long off = (row0 + r)*(long)ldA + kc + seg*8;
            *(float4*)&As[0][r][seg*8] = *(const float4*)(APh + off);
            *(float4*)&As[1][r][seg*8] = *(const float4*)(APl + off);
        }
        if (TRANSB){
            #pragma unroll
            for (int t = tid; t < 512; t += 256){
                int r = t >> 2, seg = t & 3;
                long off = (col0 + r)*(long)ldB + kc + seg*8;
                *(float4*)&Bs[0][r*40 + seg*8] = *(const float4*)(BPh + off);
                *(float4*)&Bs[1][r*40 + seg*8] = *(const float4*)(BPl + off);
            }
        } else {
            #pragma unroll
            for (int t = tid; t < 512; t += 256){
                int r = t >> 4, seg = t & 15;
                long off = (long)(kc + r)*ldB + col0 + seg*8;
                *(float4*)&Bs[0][r*136 + seg*8] = *(const float4*)(BPh + off);
                *(float4*)&Bs[1][r*136 + seg*8] = *(const float4*)(BPl + off);
            }
        }
        __syncthreads();

        #pragma unroll
        for (int ks = 0; ks < 2; ks++){
            wmma::fragment<wmma::matrix_a,16,16,16,__nv_bfloat16,wmma::row_major> afh[2], afl[2];
            #pragma unroll
            for (int i = 0; i < 2; i++){
                wmma::load_matrix_sync(afh[i], &As[0][wr*32 + i*16][ks*16], 40);
                wmma::load_matrix_sync(afl[i], &As[1][wr*32 + i*16][ks*16], 40);
            }
            if (TRANSB){
                #pragma unroll
                for (int j = 0; j < 4; j++){
                    wmma::fragment<wmma::matrix_b,16,16,16,__nv_bfloat16,wmma::col_major> bfh, bfl;
                    int nb = wc*64 + j*16;
                    wmma::load_matrix_sync(bfh, &Bs[0][nb*40 + ks*16], 40);
                    wmma::load_matrix_sync(bfl, &Bs[1][nb*40 + ks*16], 40);
                    #pragma unroll
                    for (int i = 0; i < 2; i++){
                        wmma::mma_sync(acc[i][j], afh[i], bfh, acc[i][j]);
                        wmma::mma_sync(acc[i][j], afh[i], bfl, acc[i][j]);
                        wmma::mma_sync(acc[i][j], afl[i], bfh, acc[i][j]);
                    }
                }
            } else {
                #pragma unroll
                for (int j = 0; j < 4; j++){
                    wmma::fragment<wmma::matrix_b,16,16,16,__nv_bfloat16,wmma::row_major> bfh, bfl;
                    int nb = wc*64 + j*16;
                    wmma::load_matrix_sync(bfh, &Bs[0][(ks*16)*136 + nb], 136);
                    wmma::load_matrix_sync(bfl, &Bs[1][(ks*16)*136 + nb], 136);
                    #pragma unroll
                    for (int i = 0; i < 2; i++){
                        wmma::mma_sync(acc[i][j], afh[i], bfh, acc[i][j]);
                        wmma::mma_sync(acc[i][j], afh[i], bfl, acc[i][j]);
                        wmma::mma_sync(acc[i][j], afl[i], bfh, acc[i][j]);
                    }
                }
            }
        }
        __syncthreads();
    }

    if (EPI == 2){
        #pragma unroll
        for (int i = 0; i < 2; i++)
            #pragma unroll
            for (int j = 0; j < 4; j++){
                float* cp = Cb + (row0 + wr*32 + i*16)*(long)N + col0 + wc*64 + j*16;
                wmma::store_matrix_sync(cp, acc[i][j], N, wmma::mem_row_major);
            }
        return;
    }

    float* scr = ((float*)Bs) + wid*320;   // 16x20 per warp
    float alpha = (EPI == 1) ? __ldg(alpha_p) : 1.f;
    #pragma unroll
    for (int i = 0; i < 2; i++){
        #pragma unroll
        for (int j = 0; j < 4; j++){
            wmma::store_matrix_sync(scr, acc[i][j], 20, wmma::mem_row_major);
            __syncwarp();
            #pragma unroll
            for (int e = lane; e < 256; e += 32){
                int r = e >> 4, c = e & 15;
                long grow = row0 + wr*32 + i*16 + r;
                long gcol = col0 + wc*64 + j*16 + c;
                float v = scr[r*20 + c] + bias[gcol];
                if (EPI == 0){
                    v = fmaxf(v, 0.f);
                    __nv_bfloat16 h, l;
                    bsplit(v, h, l);
                    g_hidh[grow*OH + gcol] = h;
                    g_hidl[grow*OH + gcol] = l;
                } else {
                    Cb[grow*(long)N + gcol] = v * alpha;
                }
            }
            __syncwarp();
        }
    }
}

// ============================================================
extern "C" void kernel_launch(void* const* d_in, const int* in_sizes, int n_in,
                              void* d_out, int out_size)
{
    const float* Hj   = (const float*)d_in[0];
    const float* Hi   = (const float*)d_in[1];
    const float* mask = (const float*)d_in[2];
    const float* pjw  = (const float*)d_in[3];
    const float* piw  = (const float*)d_in[4];
    const float* sw1  = (const float*)d_in[5];
    const float* sb1  = (const float*)d_in[6];
    const float* sw2  = (const float*)d_in[7];
    const float* sb2  = (const float*)d_in[8];
    const float* vw1  = (const float*)d_in[9];
    const float* vb1  = (const float*)d_in[10];
    const float* vw2  = (const float*)d_in[11];
    const float* vb2  = (const float*)d_in[12];
    const float* alpha= (const float*)d_in[13];
    float* out = (float*)d_out;

    void *pctx, *ppbh, *ppbl, *phih, *phil, *pm1h, *pm1l;
    void *pw1h, *pw1l, *phdh, *phdl, *pw2h, *pw2l;
    cudaGetSymbolAddress(&pctx, g_ctx);
    cudaGetSymbolAddress(&ppbh, g_pbh);  cudaGetSymbolAddress(&ppbl, g_pbl);
    cudaGetSymbolAddress(&phih, g_hih);  cudaGetSymbolAddress(&phil, g_hil);
    cudaGetSymbolAddress(&pm1h, g_m1h);  cudaGetSymbolAddress(&pm1l, g_m1l);
    cudaGetSymbolAddress(&pw1h, g_w1h);  cudaGetSymbolAddress(&pw1l, g_w1l);
    cudaGetSymbolAddress(&phdh, g_hidh); cudaGetSymbolAddress(&phdl, g_hidl);
    cudaGetSymbolAddress(&pw2h, g_w2h);  cudaGetSymbolAddress(&pw2l, g_w2l);

    cudaFuncSetAttribute(pair_wmma, cudaFuncAttributeMaxDynamicSharedMemorySize, PAIR_SMEM);

    // 0: proj
    proj_kernel<<<NROWS, 256>>>(Hj, Hi, pjw, piw, sw1);
    // 1: W' precompute
    wsplit_pair<<<(96*80 + 255)/256, 256>>>(sw1);
    // 2: Hi -> bf16 hi/lo
    conv_split<<<(NROWS*Hh/4 + 255)/256, 256>>>(Hi, (__nv_bfloat16*)phih,
                                                (__nv_bfloat16*)phil, NROWS*Hh/4);
    // 3: pair (profiled slot)
    pair_wmma<<<NROWS, 256, PAIR_SMEM>>>(sb1, sw2, sb2, mask);
    // 4: ctx = probs @ Hi  [NN, batched, EPI2 raw fp32]
    {
        dim3 g(Hh/128, Ss/128, Bb);
        gemm_wmma<false,2><<<g, 256>>>(
            (const __nv_bfloat16*)ppbh, (const __nv_bfloat16*)ppbl,
            (const __nv_bfloat16*)phih, (const __nv_bfloat16*)phil,
            (float*)pctx, Hh, Ss, Ss, Hh,
            (long)Ss*Ss, (long)Ss*Hh, (long)Ss*Hh, nullptr, nullptr);
    }
    // 5: msg_in -> bf16 hi/lo
    msgin_conv<<<(NROWS*(Hh/4) + 255)/256, 256>>>(Hj);
    // 6: vw1 -> bf16 hi/lo
    conv_split<<<(OH*H3/4 + 255)/256, 256>>>(vw1, (__nv_bfloat16*)pw1h,
                                             (__nv_bfloat16*)pw1l, OH*H3/4);
    // 7: hid = relu(msg_in @ vw1^T + vb1)  [NT, EPI0]
    {
        dim3 g(OH/128, NROWS/128, 1);
        gemm_wmma<true,0><<<g, 256>>>(
            (const __nv_bfloat16*)pm1h, (const __nv_bfloat16*)pm1l,
            (const __nv_bfloat16*)pw1h, (const __nv_bfloat16*)pw1l,
            nullptr, OH, H3, H3, H3,
            0, 0, 0, vb1, nullptr);
    }
    // 8: vw2 -> bf16 hi/lo
    conv_split<<<(Hh*OH/4 + 255)/256, 256>>>(vw2, (__nv_bfloat16*)pw2h,
                                             (__nv_bfloat16*)pw2l, Hh*OH/4);
    // 9: out = alpha * (hid @ vw2^T + vb2)  [NT, EPI1]
    {
        dim3 g(Hh/128, NROWS/128, 1);
        gemm_wmma<true,1><<<g, 256>>>(
            (const __nv_bfloat16*)phdh, (const __nv_bfloat16*)phdl,
            (const __nv_bfloat16*)pw2h, (const __nv_bfloat16*)pw2l,
            out, Hh, OH, OH, OH,
            0, 0, 0, vb2, alpha);
    }
    (void)in_sizes; (void)n_in; (void)out_size;
}

// round 8
// speedup vs baseline: 1.8800x; 1.1487x over previous
#include <cuda_runtime.h>
#include <cuda_bf16.h>
#include <mma.h>
#include <math.h>
#include <cstdint>

using namespace nvcuda;

#define Bb 4
#define Ss 512
#define Hh 768
#define Dd 24
#define Mm 96
#define OH 768
#define H3 2304
#define NROWS (Bb*Ss)   // 2048

typedef unsigned long long ull;

// ---- scratch ----
__device__ __align__(16) float g_Zj[NROWS*Dd];
__device__ __align__(16) float g_Zi[NROWS*Dd];
__device__ __align__(16) float g_Aj[NROWS*Mm];
__device__ __align__(16) float g_ctx[(long)NROWS*Hh];
// precomputed pair weight matrix W' = [Wc | Wd | Wb | 0]  (96 x 88, hi/lo)
__device__ __align__(16) __nv_bfloat16 g_Wph[96*88];
__device__ __align__(16) __nv_bfloat16 g_Wpl[96*88];
// bf16 hi/lo operands for tensor-core GEMMs
__device__ __align__(16) __nv_bfloat16 g_pbh[(long)Bb*Ss*Ss];
__device__ __align__(16) __nv_bfloat16 g_pbl[(long)Bb*Ss*Ss];
__device__ __align__(16) __nv_bfloat16 g_hih[(long)NROWS*Hh];
__device__ __align__(16) __nv_bfloat16 g_hil[(long)NROWS*Hh];
__device__ __align__(16) __nv_bfloat16 g_m1h[(long)NROWS*H3];
__device__ __align__(16) __nv_bfloat16 g_m1l[(long)NROWS*H3];
__device__ __align__(16) __nv_bfloat16 g_w1h[(long)OH*H3];
__device__ __align__(16) __nv_bfloat16 g_w1l[(long)OH*H3];
__device__ __align__(16) __nv_bfloat16 g_hidh[(long)NROWS*OH];
__device__ __align__(16) __nv_bfloat16 g_hidl[(long)NROWS*OH];
__device__ __align__(16) __nv_bfloat16 g_w2h[(long)Hh*OH];
__device__ __align__(16) __nv_bfloat16 g_w2l[(long)Hh*OH];

// bf16 hi/lo split
__device__ __forceinline__ void bsplit(float v, __nv_bfloat16& h, __nv_bfloat16& l){
    h = __float2bfloat16(v);
    l = __float2bfloat16(v - __bfloat162float(h));
}
__device__ __forceinline__ unsigned packhl(float v0, float v1, unsigned& lo){
    __nv_bfloat16 h0,l0,h1,l1;
    bsplit(v0, h0, l0); bsplit(v1, h1, l1);
    __nv_bfloat162 ph; ph.x = h0; ph.y = h1;
    __nv_bfloat162 pl; pl.x = l0; pl.y = l1;
    lo = *(unsigned*)&pl;
    return *(unsigned*)&ph;
}

// ============================================================
// K0: precompute W' = [Wc | Wd | Wb | 0] (96 x 88) hi/lo
// ============================================================
__global__ __launch_bounds__(256) void wsplit_pair(const float* __restrict__ sw1)
{
    int i = blockIdx.x*256 + threadIdx.x;
    if (i >= 96*88) return;
    int m = i / 88, k = i % 88;
    float wv = 0.f;
    if (k < 24)      wv = sw1[m*96 + 48 + k];
    else if (k < 48) wv = sw1[m*96 + 72 + (k-24)];
    else if (k < 72) wv = sw1[m*96 + 24 + (k-48)];
    __nv_bfloat16 h, l; bsplit(wv, h, l);
    g_Wph[i] = h; g_Wpl[i] = l;
}

// ============================================================
// K1: projections + rank-1 term Aj = Wa @ zj
// ============================================================
__global__ __launch_bounds__(256) void proj_kernel(
    const float* __restrict__ Hj, const float* __restrict__ Hi,
    const float* __restrict__ pjw, const float* __restrict__ piw,
    const float* __restrict__ sw1)
{
    int r = blockIdx.x;
    __shared__ float shj[Hh], shi[Hh], szj[Dd];
    int tid = threadIdx.x;
    for (int i = tid; i < Hh; i += 256){
        shj[i] = Hj[(long)r*Hh + i];
        shi[i] = Hi[(long)r*Hh + i];
    }
    __syncthreads();
    int o = tid >> 3, g = tid & 7;
    if (o < Dd){
        float pj = 0.f, pi = 0.f;
        for (int h = g; h < Hh; h += 8){
            pj += shj[h] * pjw[o*Hh + h];
            pi += shi[h] * piw[o*Hh + h];
        }
        #pragma unroll
        for (int d = 4; d > 0; d >>= 1){
            pj += __shfl_down_sync(0xffffffffu, pj, d, 8);
            pi += __shfl_down_sync(0xffffffffu, pi, d, 8);
        }
        if (g == 0){
            szj[o] = pj;
            g_Zj[r*Dd + o] = pj; g_Zi[r*Dd + o] = pi;
        }
    }
    __syncthreads();
    if (tid < Mm){
        float a = 0.f;
        #pragma unroll
        for (int d = 0; d < Dd; d++)
            a += sw1[tid*96 + d] * szj[d];
        g_Aj[r*Mm + tid] = a;
    }
}

// ============================================================
// K2: pair logits as WMMA GEMM + fused softmax, v3:
//  - F/W rows padded to 88 (conflict-free LDSM/STS)
//  - vectorized STS.128 F build, LDG.128 zi loads
//  - reduce scratch aliases F (barrier-protected)
// ============================================================
#define POFF_WH   0                       // 96*88*2 = 16896
#define POFF_WL   16896                   // -> 33792
#define POFF_F    33792                   // Fh [128][88]x2B = 22528
#define POFF_FL   (33792 + 22528)         // Fl -> end 78848
#define POFF_SCR  POFF_F                  // alias (26624 <= 45056)
#define POFF_SLOG 78848                   // 512 f
#define POFF_SZJ  80896
#define POFF_SSC  81024
#define POFF_SW2  81408
#define POFF_SRED 81792
#define PAIR_SMEM 81920

// compile-time column value: [u(24) | v(24) | zi(24) | 0(16)]
#define FCOLV(c) ((c) < 24 ? szj[(c)]*za[(c)] : \
                  (c) < 48 ? fabsf(szj[(c)-24]-za[(c)-24]) : \
                  (c) < 72 ? za[(c)-48] : 0.f)

__global__ __launch_bounds__(256) void pair_wmma(
    const float* __restrict__ sb1,
    const float* __restrict__ sw2v, const float* __restrict__ sb2,
    const float* __restrict__ mask)
{
    extern __shared__ char ps[];
    __nv_bfloat16* Wh = (__nv_bfloat16*)(ps + POFF_WH);
    __nv_bfloat16* Wl = (__nv_bfloat16*)(ps + POFF_WL);
    __nv_bfloat16* Fh = (__nv_bfloat16*)(ps + POFF_F);
    __nv_bfloat16* Fl = (__nv_bfloat16*)(ps + POFF_FL);
    float* scr  = (float*)(ps + POFF_SCR);
    float* slog = (float*)(ps + POFF_SLOG);
    float* szj  = (float*)(ps + POFF_SZJ);
    float* ssc  = (float*)(ps + POFF_SSC);
    float* sw2s = (float*)(ps + POFF_SW2);
    float* sred = (float*)(ps + POFF_SRED);

    int r = blockIdx.x, b = r >> 9;
    int tid = threadIdx.x, wid = tid >> 5, lane = tid & 31;

    // load precomputed W' (96*88*2B = 1056 uint4 each)
    for (int i = tid; i < 1056; i += 256){
        ((uint4*)Wh)[i] = ((const uint4*)g_Wph)[i];
        ((uint4*)Wl)[i] = ((const uint4*)g_Wpl)[i];
    }
    if (tid < Dd) szj[tid] = g_Zj[r*Dd + tid];
    if (tid < Mm){
        ssc[tid]  = g_Aj[r*Mm + tid] + sb1[tid];
        sw2s[tid] = sw2v[tid];
    }
    __syncthreads();

    int bhalf = tid >> 7;        // 0: cols 0..39, 1: cols 40..87
    int brow  = tid & 127;

    #pragma unroll 1
    for (int chunk = 0; chunk < 4; chunk++){
        // ---- build F (vectorized) ----
        {
            int t = chunk*128 + brow;
            const float4* zi4 = (const float4*)&g_Zi[(long)(b*Ss + t)*Dd];
            float za[24];
            #pragma unroll
            for (int q = 0; q < 6; q++){
                float4 v4 = __ldg(&zi4[q]);
                za[q*4+0]=v4.x; za[q*4+1]=v4.y; za[q*4+2]=v4.z; za[q*4+3]=v4.w;
            }
            if (bhalf == 0){
                uint4* dh = (uint4*)&Fh[brow*88];
                uint4* dl = (uint4*)&Fl[brow*88];
                #pragma unroll
                for (int q = 0; q < 5; q++){
                    unsigned h4[4], l4[4];
                    #pragma unroll
                    for (int e = 0; e < 4; e++){
                        int c = q*8 + e*2;
                        h4[e] = packhl(FCOLV(c), FCOLV(c+1), l4[e]);
                    }
                    dh[q] = make_uint4(h4[0],h4[1],h4[2],h4[3]);
                    dl[q] = make_uint4(l4[0],l4[1],l4[2],l4[3]);
                }
            } else {
                uint4* dh = (uint4*)&Fh[brow*88 + 40];
                uint4* dl = (uint4*)&Fl[brow*88 + 40];
                #pragma unroll
                for (int q = 0; q < 6; q++){
                    unsigned h4[4], l4[4];
                    #pragma unroll
                    for (int e = 0; e < 4; e++){
                        int c = 40 + q*8 + e*2;
                        h4[e] = packhl(FCOLV(c), FCOLV(c+1), l4[e]);
                    }
                    dh[q] = make_uint4(h4[0],h4[1],h4[2],h4[3]);
                    dl[q] = make_uint4(l4[0],l4[1],l4[2],l4[3]);
                }
            }
        }
        __syncthreads();

        // ---- GEMM: warp owns 16-row t-tile; K = 5 x 16 (cols 80..87 zero) ----
        wmma::fragment<wmma::accumulator,16,16,16,float> acc[6];
        #pragma unroll
        for (int j = 0; j < 6; j++) wmma::fill_fragment(acc[j], 0.f);

        #pragma unroll
        for (int k = 0; k < 5; k++){
            wmma::fragment<wmma::matrix_a,16,16,16,__nv_bfloat16,wmma::row_major> ah, al;
            wmma::load_matrix_sync(ah, &Fh[(wid*16)*88 + k*16], 88);
            wmma::load_matrix_sync(al, &Fl[(wid*16)*88 + k*16], 88);
            #pragma unroll
            for (int j = 0; j < 6; j++){
                wmma::fragment<wmma::matrix_b,16,16,16,__nv_bfloat16,wmma::col_major> bh, bl;
                wmma::load_matrix_sync(bh, &Wh[(j*16)*88 + k*16], 88);
                wmma::load_matrix_sync(bl, &Wl[(j*16)*88 + k*16], 88);
                wmma::mma_sync(acc[j], ah, bh, acc[j]);
                wmma::mma_sync(acc[j], ah, bl, acc[j]);
                wmma::mma_sync(acc[j], al, bh, acc[j]);
            }
        }
        __syncthreads();   // all warps done reading F before scr (alias) is written

        // ---- reduce to logits, two 48-col passes ----
        float* scrw = scr + wid*832;   // 16 x 52 floats
        int row = lane >> 1, sub = lane & 1;
        float lsum = 0.f;
        #pragma unroll
        for (int g = 0; g < 2; g++){
            #pragma unroll
            for (int j = 0; j < 3; j++)
                wmma::store_matrix_sync(scrw + j*16, acc[g*3 + j], 52, wmma::mem_row_major);
            __syncwarp();
            const float4* sr4 = (const float4*)(scrw + row*52 + sub*24);
            const float4* sc4 = (const float4*)(ssc + g*48 + sub*24);
            const float4* sw4 = (const float4*)(sw2s + g*48 + sub*24);
            #pragma unroll
            for (int q = 0; q < 6; q++){
                float4 hv = sr4[q];
                float4 cv = sc4[q];
                float4 wv = sw4[q];
                lsum += wv.x * fmaxf(hv.x + cv.x, 0.f);
                lsum += wv.y * fmaxf(hv.y + cv.y, 0.f);
                lsum += wv.z * fmaxf(hv.z + cv.z, 0.f);
                lsum += wv.w * fmaxf(hv.w + cv.w, 0.f);
            }
            __syncwarp();
        }
        lsum += __shfl_xor_sync(0xffffffffu, lsum, 1);
        if (sub == 0) slog[chunk*128 + wid*16 + row] = lsum;
        __syncthreads();
    }

    // ---- masked softmax over slog[512] ----
    int t0 = tid, t1 = tid + 256;
    float lt0 = slog[t0] + sb2[0] + (1.f - mask[b*Ss + t0]) * (-3.402823466e38f);
    float lt1 = slog[t1] + sb2[0] + (1.f - mask[b*Ss + t1]) * (-3.402823466e38f);

    float mx = fmaxf(lt0, lt1);
    #pragma unroll
    for (int d = 16; d > 0; d >>= 1)
        mx = fmaxf(mx, __shfl_xor_sync(0xffffffffu, mx, d));
    if (lane == 0) sred[wid] = mx;
    __syncthreads();
    float bmax = sred[0];
    #pragma unroll
    for (int i = 1; i < 8; i++) bmax = fmaxf(bmax, sred[i]);

    float e0 = expf(lt0 - bmax);
    float e1 = expf(lt1 - bmax);
    float sm = e0 + e1;
    #pragma unroll
    for (int d = 16; d > 0; d >>= 1)
        sm += __shfl_xor_sync(0xffffffffu, sm, d);
    __syncthreads();
    if (lane == 0) sred[wid] = sm;
    __syncthreads();
    float tot = 0.f;
    #pragma unroll
    for (int i = 0; i < 8; i++) tot += sred[i];
    float inv = 1.f / tot;

    __nv_bfloat16 h, l;
    bsplit(e0 * inv, h, l);
    g_pbh[(long)r*Ss + t0] = h; g_pbl[(long)r*Ss + t0] = l;
    bsplit(e1 * inv, h, l);
    g_pbh[(long)r*Ss + t1] = h; g_pbl[(long)r*Ss + t1] = l;
}

// ============================================================
// K3: fp32 -> bf16 hi/lo split (vectorized)
// ============================================================
__global__ __launch_bounds__(256) void conv_split(
    const float* __restrict__ x, __nv_bfloat16* __restrict__ hi,
    __nv_bfloat16* __restrict__ lo, int n4)
{
    int i = blockIdx.x*256 + threadIdx.x;
    if (i >= n4) return;
    float4 v = ((const float4*)x)[i];
    __nv_bfloat16 h0,h1,h2,h3,l0,l1,l2,l3;
    bsplit(v.x,h0,l0); bsplit(v.y,h1,l1); bsplit(v.z,h2,l2); bsplit(v.w,h3,l3);
    __nv_bfloat162 p0, p1;
    p0.x=h0; p0.y=h1; p1.x=h2; p1.y=h3;
    ((__nv_bfloat162*)hi)[2*i]   = p0;
    ((__nv_bfloat162*)hi)[2*i+1] = p1;
    p0.x=l0; p0.y=l1; p1.x=l2; p1.y=l3;
    ((__nv_bfloat162*)lo)[2*i]   = p0;
    ((__nv_bfloat162*)lo)[2*i+1] = p1;
}

// ============================================================
// K4: msg_in = [ctx | Hj | ctx*Hj] -> bf16 hi/lo
// ============================================================
__device__ __forceinline__ void store4(__nv_bfloat16* hp, __nv_bfloat16* lp,
                                       float a, float b, float c, float d)
{
    __nv_bfloat16 h0,h1,h2,h3,l0,l1,l2,l3;
    bsplit(a,h0,l0); bsplit(b,h1,l1); bsplit(c,h2,l2); bsplit(d,h3,l3);
    __nv_bfloat162 p0, p1;
    p0.x=h0; p0.y=h1; p1.x=h2; p1.y=h3;
    ((__nv_bfloat162*)hp)[0] = p0; ((__nv_bfloat162*)hp)[1] = p1;
    p0.x=l0; p0.y=l1; p1.x=l2; p1.y=l3;
    ((__nv_bfloat162*)lp)[0] = p0; ((__nv_bfloat162*)lp)[1] = p1;
}
__global__ __launch_bounds__(256) void msgin_conv(const float* __restrict__ Hj)
{
    int i = blockIdx.x*256 + threadIdx.x;
    if (i >= NROWS*(Hh/4)) return;
    int r = i / (Hh/4);
    int c = (i % (Hh/4)) * 4;
    float4 cv = *(const float4*)&g_ctx[(long)r*Hh + c];
    float4 hv = *(const float4*)&Hj[(long)r*Hh + c];
    long base = (long)r*H3 + c;
    store4(&g_m1h[base],      &g_m1l[base],      cv.x, cv.y, cv.z, cv.w);
    store4(&g_m1h[base+Hh],   &g_m1l[base+Hh],   hv.x, hv.y, hv.z, hv.w);
    store4(&g_m1h[base+2*Hh], &g_m1l[base+2*Hh],
           cv.x*hv.x, cv.y*hv.y, cv.z*hv.z, cv.w*hv.w);
}

// ============================================================
// K5: WMMA GEMM  C[M,N] = A[M,K] @ opB  (bf16 hi/lo, 3-pass)
// ============================================================
template<bool TRANSB, int EPI>
__global__ __launch_bounds__(256) void gemm_wmma(
    const __nv_bfloat16* __restrict__ Ah, const __nv_bfloat16* __restrict__ Al,
    const __nv_bfloat16* __restrict__ Bh, const __nv_bfloat16* __restrict__ Bl,
    float* __restrict__ Cout, int N, int K, int ldA, int ldB,
    long strideA, long strideB, long strideC,
    const float* __restrict__ bias, const float* __restrict__ alpha_p)
{
    __shared__ __nv_bfloat16 As[2][128][40];
    __shared__ __nv_bfloat16 Bs[2][5120];   // NT: [n][40] ; NN: [k][136]

    int tid = threadIdx.x;
    int wid = tid >> 5, lane = tid & 31;
    int wr = wid & 3, wc = wid >> 2;        // 4x2 warps, warp tile 32x64
    long row0 = (long)blockIdx.y * 128;
    long col0 = (long)blockIdx.x * 128;

    const __nv_bfloat16* APh = Ah + (long)blockIdx.z * strideA;
    const __nv_bfloat16* APl = Al + (long)blockIdx.z * strideA;
    const __nv_bfloat16* BPh = Bh + (long)blockIdx.z * strideB;
    const __nv_bfloat16* BPl = Bl + (long)blockIdx.z * strideB;
    float* Cb = Cout ? (Cout + (long)blockIdx.z * strideC) : nullptr;

    wmma::fragment<wmma::accumulator,16,16,16,float> acc[2][4];
    #pragma unroll
    for (int i = 0; i < 2; i++)
        #pragma unroll
        for (int j = 0; j < 4; j++) wmma::fill_fragment(acc[i][j], 0.f);

    #pragma unroll 1
    for (int kc = 0; kc < K; kc += 32){
        #pragma unroll
        for (int t = tid; t < 512; t += 256){
            int r = t >> 2, seg = t & 3;
            long off = (row0 + r)*(long)ldA + kc + seg*8;
            *(float4*)&As[0][r][seg*8] = *(const float4*)(APh + off);
            *(float4*)&As[1][r][seg*8] = *(const float4*)(APl + off);
        }
        if (TRANSB){
            #pragma unroll
            for (int t = tid; t < 512; t += 256){
                int r = t >> 2, seg = t & 3;
                long off = (col0 + r)*(long)ldB + kc + seg*8;
                *(float4*)&Bs[0][r*40 + seg*8] = *(const float4*)(BPh + off);
                *(float4*)&Bs[1][r*40 + seg*8] = *(const float4*)(BPl + off);
            }
        } else {
            #pragma unroll
            for (int t = tid; t < 512; t += 256){
                int r = t >> 4, seg = t & 15;
                long off = (long)(kc + r)*ldB + col0 + seg*8;
                *(float4*)&Bs[0][r*136 + seg*8] = *(const float4*)(BPh + off);
                *(float4*)&Bs[1][r*136 + seg*8] = *(const float4*)(BPl + off);
            }
        }
        __syncthreads();

        #pragma unroll
        for (int ks = 0; ks < 2; ks++){
            wmma::fragment<wmma::matrix_a,16,16,16,__nv_bfloat16,wmma::row_major> afh[2], afl[2];
            #pragma unroll
            for (int i = 0; i < 2; i++){
                wmma::load_matrix_sync(afh[i], &As[0][wr*32 + i*16][ks*16], 40);
                wmma::load_matrix_sync(afl[i], &As[1][wr*32 + i*16][ks*16], 40);
            }
            if (TRANSB){
                #pragma unroll
                for (int j = 0; j < 4; j++){
                    wmma::fragment<wmma::matrix_b,16,16,16,__nv_bfloat16,wmma::col_major> bfh, bfl;
                    int nb = wc*64 + j*16;
                    wmma::load_matrix_sync(bfh, &Bs[0][nb*40 + ks*16], 40);
                    wmma::load_matrix_sync(bfl, &Bs[1][nb*40 + ks*16], 40);
                    #pragma unroll
                    for (int i = 0; i < 2; i++){
                        wmma::mma_sync(acc[i][j], afh[i], bfh, acc[i][j]);
                        wmma::mma_sync(acc[i][j], afh[i], bfl, acc[i][j]);
                        wmma::mma_sync(acc[i][j], afl[i], bfh, acc[i][j]);
                    }
                }
            } else {
                #pragma unroll
                for (int j = 0; j < 4; j++){
                    wmma::fragment<wmma::matrix_b,16,16,16,__nv_bfloat16,wmma::row_major> bfh, bfl;
                    int nb = wc*64 + j*16;
                    wmma::load_matrix_sync(bfh, &Bs[0][(ks*16)*136 + nb], 136);
                    wmma::load_matrix_sync(bfl, &Bs[1][(ks*16)*136 + nb], 136);
                    #pragma unroll
                    for (int i = 0; i < 2; i++){
                        wmma::mma_sync(acc[i][j], afh[i], bfh, acc[i][j]);
                        wmma::mma_sync(acc[i][j], afh[i], bfl, acc[i][j]);
                        wmma::mma_sync(acc[i][j], afl[i], bfh, acc[i][j]);
                    }
                }
            }
        }
        __syncthreads();
    }

    if (EPI == 2){
        #pragma unroll
        for (int i = 0; i < 2; i++)
            #pragma unroll
            for (int j = 0; j < 4; j++){
                float* cp = Cb + (row0 + wr*32 + i*16)*(long)N + col0 + wc*64 + j*16;
                wmma::store_matrix_sync(cp, acc[i][j], N, wmma::mem_row_major);
            }
        return;
    }

    float* scr = ((float*)Bs) + wid*320;   // 16x20 per warp
    float alpha = (EPI == 1) ? __ldg(alpha_p) : 1.f;
    #pragma unroll
    for (int i = 0; i < 2; i++){
        #pragma unroll
        for (int j = 0; j < 4; j++){
            wmma::store_matrix_sync(scr, acc[i][j], 20, wmma::mem_row_major);
            __syncwarp();
            #pragma unroll
            for (int e = lane; e < 256; e += 32){
                int r = e >> 4, c = e & 15;
                long grow = row0 + wr*32 + i*16 + r;
                long gcol = col0 + wc*64 + j*16 + c;
                float v = scr[r*20 + c] + bias[gcol];
                if (EPI == 0){
                    v = fmaxf(v, 0.f);
                    __nv_bfloat16 h, l;
                    bsplit(v, h, l);
                    g_hidh[grow*OH + gcol] = h;
                    g_hidl[grow*OH + gcol] = l;
                } else {
                    Cb[grow*(long)N + gcol] = v * alpha;
                }
            }
            __syncwarp();
        }
    }
}

// ============================================================
extern "C" void kernel_launch(void* const* d_in, const int* in_sizes, int n_in,
                              void* d_out, int out_size)
{
    const float* Hj   = (const float*)d_in[0];
    const float* Hi   = (const float*)d_in[1];
    const float* mask = (const float*)d_in[2];
    const float* pjw  = (const float*)d_in[3];
    const float* piw  = (const float*)d_in[4];
    const float* sw1  = (const float*)d_in[5];
    const float* sb1  = (const float*)d_in[6];
    const float* sw2  = (const float*)d_in[7];
    const float* sb2  = (const float*)d_in[8];
    const float* vw1  = (const float*)d_in[9];
    const float* vb1  = (const float*)d_in[10];
    const float* vw2  = (const float*)d_in[11];
    const float* vb2  = (const float*)d_in[12];
    const float* alpha= (const float*)d_in[13];
    float* out = (float*)d_out;

    void *pctx, *ppbh, *ppbl, *phih, *phil, *pm1h, *pm1l;
    void *pw1h, *pw1l, *phdh, *phdl, *pw2h, *pw2l;
    cudaGetSymbolAddress(&pctx, g_ctx);
    cudaGetSymbolAddress(&ppbh, g_pbh);  cudaGetSymbolAddress(&ppbl, g_pbl);
    cudaGetSymbolAddress(&phih, g_hih);  cudaGetSymbolAddress(&phil, g_hil);
    cudaGetSymbolAddress(&pm1h, g_m1h);  cudaGetSymbolAddress(&pm1l, g_m1l);
    cudaGetSymbolAddress(&pw1h, g_w1h);  cudaGetSymbolAddress(&pw1l, g_w1l);
    cudaGetSymbolAddress(&phdh, g_hidh); cudaGetSymbolAddress(&phdl, g_hidl);
    cudaGetSymbolAddress(&pw2h, g_w2h);  cudaGetSymbolAddress(&pw2l, g_w2l);

    cudaFuncSetAttribute(pair_wmma, cudaFuncAttributeMaxDynamicSharedMemorySize, PAIR_SMEM);

    // 0: proj
    proj_kernel<<<NROWS, 256>>>(Hj, Hi, pjw, piw, sw1);
    // 1: W' precompute
    wsplit_pair<<<(96*88 + 255)/256, 256>>>(sw1);
    // 2: Hi -> bf16 hi/lo
    conv_split<<<(NROWS*Hh/4 + 255)/256, 256>>>(Hi, (__nv_bfloat16*)phih,
                                                (__nv_bfloat16*)phil, NROWS*Hh/4);
    // 3: pair (profiled slot)
    pair_wmma<<<NROWS, 256, PAIR_SMEM>>>(sb1, sw2, sb2, mask);
    // 4: ctx = probs @ Hi  [NN, batched, EPI2 raw fp32]
    {
        dim3 g(Hh/128, Ss/128, Bb);
        gemm_wmma<false,2><<<g, 256>>>(
            (const __nv_bfloat16*)ppbh, (const __nv_bfloat16*)ppbl,
            (const __nv_bfloat16*)phih, (const __nv_bfloat16*)phil,
            (float*)pctx, Hh, Ss, Ss, Hh,
            (long)Ss*Ss, (long)Ss*Hh, (long)Ss*Hh, nullptr, nullptr);
    }
    // 5: msg_in -> bf16 hi/lo
    msgin_conv<<<(NROWS*(Hh/4) + 255)/256, 256>>>(Hj);
    // 6: vw1 -> bf16 hi/lo
    conv_split<<<(OH*H3/4 + 255)/256, 256>>>(vw1, (__nv_bfloat16*)pw1h,
                                             (__nv_bfloat16*)pw1l, OH*H3/4);
    // 7: hid = relu(msg_in @ vw1^T + vb1)  [NT, EPI0]
    {
        dim3 g(OH/128, NROWS/128, 1);
        gemm_wmma<true,0><<<g, 256>>>(
            (const __nv_bfloat16*)pm1h, (const __nv_bfloat16*)pm1l,
            (const __nv_bfloat16*)pw1h, (const __nv_bfloat16*)pw1l,
            nullptr, OH, H3, H3, H3,
            0, 0, 0, vb1, nullptr);
    }
    // 8: vw2 -> bf16 hi/lo
    conv_split<<<(Hh*OH/4 + 255)/256, 256>>>(vw2, (__nv_bfloat16*)pw2h,
                                             (__nv_bfloat16*)pw2l, Hh*OH/4);
    // 9: out = alpha * (hid @ vw2^T + vb2)  [NT, EPI1]
    {
        dim3 g(Hh/128, NROWS/128, 1);
        gemm_wmma<true,1><<<g, 256>>>(
            (const __nv_bfloat16*)phdh, (const __nv_bfloat16*)phdl,
            (const __nv_bfloat16*)pw2h, (const __nv_bfloat16*)pw2l,
            out, Hh, OH, OH, OH,
            0, 0, 0, vb2, alpha);
    }
    (void)in_sizes; (void)n_in; (void)out_size;
}